// round 2
// baseline (speedup 1.0000x reference)
#include <cuda_runtime.h>
#include <cstdint>

#define SLOPE 0.01f
#define BN_EPS 1e-5f

// Fixed problem sizes (from setup_inputs): N_in=80000, N_out=200000, Cin=128, Cout=64
#define MAX_NIN   80000
#define MAX_NOUT  200000
#define RED_BLOCKS 240

// Scratch (static device globals — no allocation allowed)
__device__ float g_h [MAX_NIN  * 64];
__device__ float g_u [MAX_NOUT * 64];
__device__ float g_t1[MAX_NOUT * 64];
__device__ float g_t2[MAX_NOUT * 64];
__device__ float g_t3[MAX_NOUT * 64];
__device__ float g_part[RED_BLOCKS * 128];
__device__ float g_ab[4 * 128];   // per BN stage: a[64], b[64]

// ---------------------------------------------------------------------------
// Gather-GEMM conv:  out[n,d] = sum_k sum_c feats[nbr[k,n], c] * W[k,c,d]
// Optional affine (fused BN of previous stage) applied to gathered values;
// sentinel idx >= Nsrc yields exact zero row (matches reference pad order).
// MODE 0: out = lrelu(acc)   MODE 1: out = acc + skip
// Block: 64 output points x 64 Cout, 256 threads, 4x4 microtile.
// ---------------------------------------------------------------------------
template<int KK, int CIN, bool AFF, int MODE>
__global__ __launch_bounds__(256)
void conv_kernel(const float* __restrict__ feats,
                 const float* __restrict__ W,
                 const int*   __restrict__ nbr,
                 const float* __restrict__ ab,
                 const float* __restrict__ skip,
                 float*       __restrict__ out,
                 int Nsrc, int Nout)
{
    __shared__ float As[64][68];   // [row][c] (padded)
    __shared__ float Bs[64][64];   // [c][d]
    __shared__ int   sIdx[64];
    __shared__ float sA[64], sB[64];

    const int tid = threadIdx.x;
    const int tx  = tid & 15;      // cout group (4 couts)
    const int ty  = tid >> 4;      // row group  (4 rows)
    const int n0  = blockIdx.x * 64;

    float acc[4][4];
    #pragma unroll
    for (int i = 0; i < 4; ++i)
        #pragma unroll
        for (int j = 0; j < 4; ++j) acc[i][j] = 0.f;

    if (AFF && tid < 64) { sA[tid] = ab[tid]; sB[tid] = ab[64 + tid]; }

    for (int k = 0; k < KK; ++k) {
        if (tid < 64) sIdx[tid] = nbr[k * Nout + n0 + tid];
        __syncthreads();

        #pragma unroll
        for (int chunk = 0; chunk < CIN; chunk += 64) {
            // --- gather A tile: 64 rows x 64 cols (this Cin chunk) ---
            #pragma unroll
            for (int i = 0; i < 4; ++i) {
                const int row = (tid >> 4) + i * 16;
                const int cg  = tid & 15;
                const int idx = sIdx[row];
                float4 v;
                if (idx < Nsrc) {
                    v = *(const float4*)&feats[(long long)idx * CIN + chunk + cg * 4];
                    if (AFF) {   // only for CIN==64 stages (chunk==0)
                        const int c = cg * 4;
                        v.x = v.x * sA[c + 0] + sB[c + 0];
                        v.y = v.y * sA[c + 1] + sB[c + 1];
                        v.z = v.z * sA[c + 2] + sB[c + 2];
                        v.w = v.w * sA[c + 3] + sB[c + 3];
                    }
                } else {
                    v = make_float4(0.f, 0.f, 0.f, 0.f);
                }
                *(float4*)&As[row][cg * 4] = v;
            }
            // --- load W tile: 64 x 64 ---
            {
                const float4* Wk = (const float4*)(W + ((long long)k * CIN + chunk) * 64);
                float4* Bp = (float4*)&Bs[0][0];
                #pragma unroll
                for (int i = 0; i < 4; ++i)
                    Bp[tid + i * 256] = Wk[tid + i * 256];
            }
            __syncthreads();

            // --- 64x64x64 FFMA core ---
            #pragma unroll
            for (int cc = 0; cc < 64; ++cc) {
                const float a0 = As[ty * 4 + 0][cc];
                const float a1 = As[ty * 4 + 1][cc];
                const float a2 = As[ty * 4 + 2][cc];
                const float a3 = As[ty * 4 + 3][cc];
                const float4 b = *(const float4*)&Bs[cc][tx * 4];
                acc[0][0] += a0 * b.x; acc[0][1] += a0 * b.y; acc[0][2] += a0 * b.z; acc[0][3] += a0 * b.w;
                acc[1][0] += a1 * b.x; acc[1][1] += a1 * b.y; acc[1][2] += a1 * b.z; acc[1][3] += a1 * b.w;
                acc[2][0] += a2 * b.x; acc[2][1] += a2 * b.y; acc[2][2] += a2 * b.z; acc[2][3] += a2 * b.w;
                acc[3][0] += a3 * b.x; acc[3][1] += a3 * b.y; acc[3][2] += a3 * b.z; acc[3][3] += a3 * b.w;
            }
            __syncthreads();
        }
    }

    // --- epilogue ---
    #pragma unroll
    for (int i = 0; i < 4; ++i) {
        const long long row = n0 + ty * 4 + i;
        float4 v = make_float4(acc[i][0], acc[i][1], acc[i][2], acc[i][3]);
        if (MODE == 1) {
            const float4 s = *(const float4*)&skip[row * 64 + tx * 4];
            v.x += s.x; v.y += s.y; v.z += s.z; v.w += s.w;
        } else {
            v.x = v.x >= 0.f ? v.x : SLOPE * v.x;
            v.y = v.y >= 0.f ? v.y : SLOPE * v.y;
            v.z = v.z >= 0.f ? v.z : SLOPE * v.z;
            v.w = v.w >= 0.f ? v.w : SLOPE * v.w;
        }
        *(float4*)&out[row * 64 + tx * 4] = v;
    }
}

// ---------------------------------------------------------------------------
// BN stats: stage 1 — per-block partial sums / sumsq (deterministic, no atomics)
// ---------------------------------------------------------------------------
__global__ __launch_bounds__(256)
void reduce_stats(const float* __restrict__ t, int N, float* __restrict__ partial)
{
    const int ch  = threadIdx.x & 63;
    const int sub = threadIdx.x >> 6;    // 0..3
    float s = 0.f, ss = 0.f;
    for (int row = blockIdx.x * 4 + sub; row < N; row += gridDim.x * 4) {
        const float v = t[(long long)row * 64 + ch];
        s += v; ss += v * v;
    }
    __shared__ float sh[2][4][64];
    sh[0][sub][ch] = s;
    sh[1][sub][ch] = ss;
    __syncthreads();
    if (threadIdx.x < 64) {
        const float S  = sh[0][0][ch] + sh[0][1][ch] + sh[0][2][ch] + sh[0][3][ch];
        const float SS = sh[1][0][ch] + sh[1][1][ch] + sh[1][2][ch] + sh[1][3][ch];
        partial[blockIdx.x * 128 + ch]      = S;
        partial[blockIdx.x * 128 + 64 + ch] = SS;
    }
}

// Stage 2 — finalize mean/var -> affine a,b (64 threads, fixed order, double acc)
__global__ void finalize_stats(const float* __restrict__ partial, int nblk, float invN,
                               const float* __restrict__ gamma, const float* __restrict__ beta,
                               float* __restrict__ ab)
{
    const int ch = threadIdx.x;
    if (ch >= 64) return;
    double s = 0.0, ss = 0.0;
    for (int b = 0; b < nblk; ++b) {
        s  += (double)partial[b * 128 + ch];
        ss += (double)partial[b * 128 + 64 + ch];
    }
    const float m   = (float)(s * (double)invN);
    const float var = (float)(ss * (double)invN) - m * m;
    const float inv = rsqrtf(var + BN_EPS);
    const float a   = gamma[ch] * inv;
    ab[ch]      = a;
    ab[64 + ch] = beta[ch] - m * a;
}

// Final: out = t * a[ch] + b[ch]  (vectorized; 16 float4 per row of 64 channels)
__global__ __launch_bounds__(256)
void apply_affine(const float* __restrict__ t, const float* __restrict__ ab,
                  float* __restrict__ out, int total4)
{
    const int i = blockIdx.x * blockDim.x + threadIdx.x;
    if (i >= total4) return;
    float4 v = ((const float4*)t)[i];
    const int c = (i & 15) * 4;
    v.x = v.x * ab[c + 0] + ab[64 + c + 0];
    v.y = v.y * ab[c + 1] + ab[64 + c + 1];
    v.z = v.z * ab[c + 2] + ab[64 + c + 2];
    v.w = v.w * ab[c + 3] + ab[64 + c + 3];
    ((float4*)out)[i] = v;
}

// ---------------------------------------------------------------------------
extern "C" void kernel_launch(void* const* d_in, const int* in_sizes, int n_in,
                              void* d_out, int out_size)
{
    const float* x      = (const float*)d_in[0];
    const float* skip   = (const float*)d_in[1];
    const int*   nbr_t  = (const int*)d_in[2];
    const int*   nbr_up = (const int*)d_in[3];
    const int*   nbr1   = (const int*)d_in[4];
    const int*   nbr2   = (const int*)d_in[5];
    const int*   nbr3   = (const int*)d_in[6];
    const float* Wt     = (const float*)d_in[7];
    const float* Wu     = (const float*)d_in[8];
    const float* W1     = (const float*)d_in[9];
    const float* W2     = (const float*)d_in[10];
    const float* W3     = (const float*)d_in[11];
    const float* gt = (const float*)d_in[12]; const float* bt = (const float*)d_in[13];
    const float* g1 = (const float*)d_in[14]; const float* b1 = (const float*)d_in[15];
    const float* g2 = (const float*)d_in[16]; const float* b2 = (const float*)d_in[17];
    const float* g3 = (const float*)d_in[18]; const float* b3 = (const float*)d_in[19];

    const int N_in  = in_sizes[0] / 128;   // 80000
    const int N_out = in_sizes[1] / 64;    // 200000
    float* out = (float*)d_out;

    float *h_, *u_, *t1_, *t2_, *t3_, *part_, *ab_;
    cudaGetSymbolAddress((void**)&h_,    g_h);
    cudaGetSymbolAddress((void**)&u_,    g_u);
    cudaGetSymbolAddress((void**)&t1_,   g_t1);
    cudaGetSymbolAddress((void**)&t2_,   g_t2);
    cudaGetSymbolAddress((void**)&t3_,   g_t3);
    cudaGetSymbolAddress((void**)&part_, g_part);
    cudaGetSymbolAddress((void**)&ab_,   g_ab);

    const int gin  = N_in  / 64;   // 1250
    const int gout = N_out / 64;   // 3125

    // 1. trans conv (Cin=128) + lrelu -> g_h ; BN stats -> ab[0]
    conv_kernel<27, 128, false, 0><<<gin, 256>>>(x, Wt, nbr_t, nullptr, nullptr, h_, N_in, N_in);
    reduce_stats<<<RED_BLOCKS, 256>>>(h_, N_in, part_);
    finalize_stats<<<1, 64>>>(part_, RED_BLOCKS, 1.0f / N_in, gt, bt, ab_ + 0);

    // 2. inverse conv (gather of BN'd h) + skip -> g_u
    conv_kernel<27, 64, true, 1><<<gout, 256>>>(h_, Wu, nbr_up, ab_ + 0, skip, u_, N_in, N_out);

    // 3. conv1 + lrelu -> t1 ; stats -> ab[1]
    conv_kernel<9, 64, false, 0><<<gout, 256>>>(u_, W1, nbr1, nullptr, nullptr, t1_, N_out, N_out);
    reduce_stats<<<RED_BLOCKS, 256>>>(t1_, N_out, part_);
    finalize_stats<<<1, 64>>>(part_, RED_BLOCKS, 1.0f / N_out, g1, b1, ab_ + 128);

    // 4. conv2 (gather applies BN1) + lrelu -> t2 ; stats -> ab[2]
    conv_kernel<9, 64, true, 0><<<gout, 256>>>(t1_, W2, nbr2, ab_ + 128, nullptr, t2_, N_out, N_out);
    reduce_stats<<<RED_BLOCKS, 256>>>(t2_, N_out, part_);
    finalize_stats<<<1, 64>>>(part_, RED_BLOCKS, 1.0f / N_out, g2, b2, ab_ + 256);

    // 5. conv3 (gather applies BN2) + lrelu -> t3 ; stats -> ab[3]
    conv_kernel<27, 64, true, 0><<<gout, 256>>>(t2_, W3, nbr3, ab_ + 256, nullptr, t3_, N_out, N_out);
    reduce_stats<<<RED_BLOCKS, 256>>>(t3_, N_out, part_);
    finalize_stats<<<1, 64>>>(part_, RED_BLOCKS, 1.0f / N_out, g3, b3, ab_ + 384);

    // 6. final BN3 apply -> d_out
    const int total4 = N_out * 16;
    apply_affine<<<(total4 + 255) / 256, 256>>>(t3_, ab_ + 384, out, total4);
}

// round 6
// speedup vs baseline: 1.0839x; 1.0839x over previous
#include <cuda_runtime.h>
#include <cuda_bf16.h>
#include <cstdint>

#define SLOPE 0.01f
#define BN_EPS 1e-5f

#define MAX_NIN   80000
#define MAX_NOUT  200000
#define RED_BLOCKS 240

// Scratch (static device globals — no allocation allowed)
__device__ float    g_h [MAX_NIN  * 64];
__device__ float    g_u [MAX_NOUT * 64];
__device__ float    g_t1[MAX_NOUT * 64];
__device__ float    g_t2[MAX_NOUT * 64];
__device__ float    g_t3[MAX_NOUT * 64];
__device__ float    g_part[RED_BLOCKS * 128];
__device__ float    g_ab[4 * 128];              // per BN stage: a[64], b[64]
__device__ uint32_t g_Bimg[27 * 4 * 2048];      // split/packed/swizzled bf16 weights

// ---------------------------------------------------------------------------
// helpers
// ---------------------------------------------------------------------------
__device__ __forceinline__ uint32_t packbf(float a, float b) {
    __nv_bfloat162 t = __floats2bfloat162_rn(a, b);   // .x in low 16 bits
    return *reinterpret_cast<uint32_t*>(&t);
}

// m16n8k16 bf16 MMA (sm_80+ path; valid on compute_103)
__device__ __forceinline__ void mma_bf16(float* c, const uint32_t* a, const uint32_t* b) {
    asm volatile(
        "mma.sync.aligned.m16n8k16.row.col.f32.bf16.bf16.f32 "
        "{%0,%1,%2,%3}, {%4,%5,%6,%7}, {%8,%9}, {%0,%1,%2,%3};"
        : "+f"(c[0]), "+f"(c[1]), "+f"(c[2]), "+f"(c[3])
        : "r"(a[0]), "r"(a[1]), "r"(a[2]), "r"(a[3]), "r"(b[0]), "r"(b[1]));
}

// Swizzled index into a [rows x 32] u32 tile (conflict-free for frag access)
__device__ __forceinline__ int sidx(int row, int col) {
    return row * 32 + (col ^ ((row & 7) * 4));
}

// SMEM layout (u32 units): A 2x4096 (128x32), B 2x2048 (64x32), affine 128 floats
#define F_A0 0
#define F_A1 4096
#define F_B0 8192
#define F_B1 10240
#define F_AV 12288
#define F_BV 12352
#define SMEM_BYTES (12416 * 4)

// ---------------------------------------------------------------------------
// Weight pre-transform: per chunk (= one 32-wide Cin slice of one tap) build a
// 64x32 u32 tile: cols 0-15 = hi bf16x2 plane, 16-31 = lo plane, pre-swizzled.
// One thread per (chunk, kp, n).
// ---------------------------------------------------------------------------
__global__ void transpose_W(const float* __restrict__ W, uint32_t* __restrict__ Bimg,
                            int total)
{
    const int e = blockIdx.x * 256 + threadIdx.x;
    if (e >= total) return;
    const int chunk = e >> 10;          // k*NSUB + s
    const int kp    = (e >> 6) & 15;    // k-pair within chunk (0..15)
    const int n     = e & 63;           // Cout
    const int kbase = chunk * 32 + kp * 2;   // == (k*CIN + s*32) + 2*kp
    const float w0 = W[(size_t)kbase * 64 + n];
    const float w1 = W[(size_t)(kbase + 1) * 64 + n];
    const __nv_bfloat16 h0 = __float2bfloat16_rn(w0);
    const __nv_bfloat16 h1 = __float2bfloat16_rn(w1);
    const float r0 = w0 - __bfloat162float(h0);
    const float r1 = w1 - __bfloat162float(h1);
    uint32_t* dst = Bimg + (size_t)chunk * 2048;
    dst[sidx(n, kp)]      = packbf(w0, w1);   // hi plane
    dst[sidx(n, 16 + kp)] = packbf(r0, r1);   // lo plane
}

// ---------------------------------------------------------------------------
// bf16 split-2 mma.sync gather-GEMM conv (3 MMA terms: HH + HL + LH).
// Tile: 128 output points x 64 Cout; 8 warps (4x2), warp tile 32x32.
// K consumed in 32-float chunks, double-buffered SMEM; gather LDG for chunk
// i+1 issued before the MMA block of chunk i.
// MODE 0: out = lrelu(acc)    MODE 1: out = acc + skip
// ---------------------------------------------------------------------------
template<int KK, int CIN, bool AFF, int MODE>
__global__ __launch_bounds__(256)
void conv_mma(const float* __restrict__ feats,
              const uint32_t* __restrict__ Bimg,
              const int*   __restrict__ nbr,
              const float* __restrict__ ab,
              const float* __restrict__ skip,
              float*       __restrict__ out,
              int Nsrc, int Nout)
{
    constexpr int NSUB = CIN / 32;
    constexpr int NCH  = KK * NSUB;

    extern __shared__ uint32_t smu[];
    float* sAv = (float*)(smu + F_AV);
    float* sBv = (float*)(smu + F_BV);

    const int tid  = threadIdx.x;
    const int lane = tid & 31, wid = tid >> 5;
    const int g    = lane >> 2, t4 = lane & 3;     // groupID, threadID_in_group
    const int wm   = wid & 3,  wn  = wid >> 2;     // warp tile coords (4 x 2)
    const int n0   = blockIdx.x * 128;
    const int row  = tid & 127, h = tid >> 7;      // gather: row + 16-col half

    if (AFF && tid < 64) { sAv[tid] = ab[tid]; sBv[tid] = ab[64 + tid]; }
    __syncthreads();

    float acc[2][4][4];
    #pragma unroll
    for (int mm = 0; mm < 2; ++mm)
        #pragma unroll
        for (int nn = 0; nn < 4; ++nn)
            #pragma unroll
            for (int q = 0; q < 4; ++q) acc[mm][nn][q] = 0.f;

    float4 pa[4];
    uint4  pbu[2];

    auto loadG = [&](int c) {
        const int k = c / NSUB, s = c - k * NSUB;
        const int gr = n0 + row;
        int idx = Nsrc;                                   // sentinel -> zero row
        if (gr < Nout) idx = nbr[(size_t)k * Nout + gr];
        const bool valid = (unsigned)idx < (unsigned)Nsrc;
        const float* src = feats + (size_t)idx * CIN + s * 32 + h * 16;
        #pragma unroll
        for (int j = 0; j < 4; ++j) {
            float4 v = make_float4(0.f, 0.f, 0.f, 0.f);
            if (valid) {
                v = *(const float4*)(src + j * 4);
                if (AFF) {
                    const int cc = s * 32 + h * 16 + j * 4;
                    v.x = v.x * sAv[cc + 0] + sBv[cc + 0];
                    v.y = v.y * sAv[cc + 1] + sBv[cc + 1];
                    v.z = v.z * sAv[cc + 2] + sBv[cc + 2];
                    v.w = v.w * sAv[cc + 3] + sBv[cc + 3];
                }
            }
            pa[j] = v;
        }
        const uint4* bsrc = (const uint4*)(Bimg + (size_t)c * 2048);
        pbu[0] = bsrc[tid];
        pbu[1] = bsrc[tid + 256];
    };

    auto stsF = [&](int c) {
        const int buf = c & 1;
        uint32_t* A_ = smu + (buf ? F_A1 : F_A0);
        uint32_t* B_ = smu + (buf ? F_B1 : F_B0);
        uint32_t hi[8], lo[8];
        #pragma unroll
        for (int j = 0; j < 4; ++j) {
            const float4 v = pa[j];
            const __nv_bfloat16 hx = __float2bfloat16_rn(v.x);
            const __nv_bfloat16 hy = __float2bfloat16_rn(v.y);
            const __nv_bfloat16 hz = __float2bfloat16_rn(v.z);
            const __nv_bfloat16 hw = __float2bfloat16_rn(v.w);
            hi[j * 2 + 0] = packbf(v.x, v.y);
            hi[j * 2 + 1] = packbf(v.z, v.w);
            lo[j * 2 + 0] = packbf(v.x - __bfloat162float(hx), v.y - __bfloat162float(hy));
            lo[j * 2 + 1] = packbf(v.z - __bfloat162float(hz), v.w - __bfloat162float(hw));
        }
        // hi plane cols [h*8, h*8+8), lo plane cols [16+h*8, 16+h*8+8)
        *(uint4*)&A_[sidx(row, h * 8 + 0)]      = make_uint4(hi[0], hi[1], hi[2], hi[3]);
        *(uint4*)&A_[sidx(row, h * 8 + 4)]      = make_uint4(hi[4], hi[5], hi[6], hi[7]);
        *(uint4*)&A_[sidx(row, 16 + h * 8 + 0)] = make_uint4(lo[0], lo[1], lo[2], lo[3]);
        *(uint4*)&A_[sidx(row, 16 + h * 8 + 4)] = make_uint4(lo[4], lo[5], lo[6], lo[7]);
        // B image is pre-swizzled: pure linear copy
        ((uint4*)B_)[tid]       = pbu[0];
        ((uint4*)B_)[tid + 256] = pbu[1];
    };

    auto compute = [&](int buf) {
        const uint32_t* A_ = smu + (buf ? F_A1 : F_A0);
        const uint32_t* B_ = smu + (buf ? F_B1 : F_B0);
        #pragma unroll
        for (int ks = 0; ks < 2; ++ks) {
            const int kc = ks * 8 + t4;        // hi-plane col (lo = +16)
            uint32_t ah[2][4], al[2][4], bh[4][2], bl[4][2];
            #pragma unroll
            for (int mm = 0; mm < 2; ++mm) {
                const int r0 = wm * 32 + mm * 16 + g;
                ah[mm][0] = A_[sidx(r0,     kc)];
                ah[mm][1] = A_[sidx(r0 + 8, kc)];
                ah[mm][2] = A_[sidx(r0,     kc + 4)];
                ah[mm][3] = A_[sidx(r0 + 8, kc + 4)];
                al[mm][0] = A_[sidx(r0,     16 + kc)];
                al[mm][1] = A_[sidx(r0 + 8, 16 + kc)];
                al[mm][2] = A_[sidx(r0,     16 + kc + 4)];
                al[mm][3] = A_[sidx(r0 + 8, 16 + kc + 4)];
            }
            #pragma unroll
            for (int nn = 0; nn < 4; ++nn) {
                const int cN = wn * 32 + nn * 8 + g;
                bh[nn][0] = B_[sidx(cN, kc)];
                bh[nn][1] = B_[sidx(cN, kc + 4)];
                bl[nn][0] = B_[sidx(cN, 16 + kc)];
                bl[nn][1] = B_[sidx(cN, 16 + kc + 4)];
            }
            #pragma unroll
            for (int mm = 0; mm < 2; ++mm)
                #pragma unroll
                for (int nn = 0; nn < 4; ++nn) {
                    mma_bf16(acc[mm][nn], ah[mm], bh[nn]);
                    mma_bf16(acc[mm][nn], ah[mm], bl[nn]);
                    mma_bf16(acc[mm][nn], al[mm], bh[nn]);
                }
        }
    };

    loadG(0);
    stsF(0);
    __syncthreads();
    for (int c = 0; c < NCH; ++c) {
        if (c + 1 < NCH) loadG(c + 1);
        compute(c & 1);
        if (c + 1 < NCH) stsF(c + 1);
        __syncthreads();
    }

    // --- epilogue ---
    #pragma unroll
    for (int mm = 0; mm < 2; ++mm) {
        #pragma unroll
        for (int half = 0; half < 2; ++half) {
            const int r = n0 + wm * 32 + mm * 16 + g + half * 8;
            if (r < Nout) {
                #pragma unroll
                for (int nn = 0; nn < 4; ++nn) {
                    float v0 = acc[mm][nn][half * 2 + 0];
                    float v1 = acc[mm][nn][half * 2 + 1];
                    const int col = wn * 32 + nn * 8 + t4 * 2;
                    if (MODE == 1) {
                        const float2 s2 = *(const float2*)&skip[(size_t)r * 64 + col];
                        v0 += s2.x; v1 += s2.y;
                    } else {
                        v0 = v0 >= 0.f ? v0 : SLOPE * v0;
                        v1 = v1 >= 0.f ? v1 : SLOPE * v1;
                    }
                    *(float2*)&out[(size_t)r * 64 + col] = make_float2(v0, v1);
                }
            }
        }
    }
}

// ---------------------------------------------------------------------------
// BN stats (deterministic, two-stage)
// ---------------------------------------------------------------------------
__global__ __launch_bounds__(256)
void reduce_stats(const float* __restrict__ t, int N, float* __restrict__ partial)
{
    const int ch  = threadIdx.x & 63;
    const int sub = threadIdx.x >> 6;
    float s = 0.f, ss = 0.f;
    for (int row = blockIdx.x * 4 + sub; row < N; row += gridDim.x * 4) {
        const float v = t[(size_t)row * 64 + ch];
        s += v; ss += v * v;
    }
    __shared__ float sh[2][4][64];
    sh[0][sub][ch] = s;
    sh[1][sub][ch] = ss;
    __syncthreads();
    if (threadIdx.x < 64) {
        partial[blockIdx.x * 128 + ch]      = sh[0][0][ch] + sh[0][1][ch] + sh[0][2][ch] + sh[0][3][ch];
        partial[blockIdx.x * 128 + 64 + ch] = sh[1][0][ch] + sh[1][1][ch] + sh[1][2][ch] + sh[1][3][ch];
    }
}

__global__ void finalize_stats(const float* __restrict__ partial, int nblk, float invN,
                               const float* __restrict__ gamma, const float* __restrict__ beta,
                               float* __restrict__ ab)
{
    const int ch = threadIdx.x;
    if (ch >= 64) return;
    double s = 0.0, ss = 0.0;
    for (int b = 0; b < nblk; ++b) {
        s  += (double)partial[b * 128 + ch];
        ss += (double)partial[b * 128 + 64 + ch];
    }
    const float m   = (float)(s * (double)invN);
    const float var = (float)(ss * (double)invN) - m * m;
    const float inv = rsqrtf(var + BN_EPS);
    const float a   = gamma[ch] * inv;
    ab[ch]      = a;
    ab[64 + ch] = beta[ch] - m * a;
}

__global__ __launch_bounds__(256)
void apply_affine(const float* __restrict__ t, const float* __restrict__ ab,
                  float* __restrict__ out, int total4)
{
    const int i = blockIdx.x * blockDim.x + threadIdx.x;
    if (i >= total4) return;
    float4 v = ((const float4*)t)[i];
    const int c = (i & 15) * 4;
    v.x = v.x * ab[c + 0] + ab[64 + c + 0];
    v.y = v.y * ab[c + 1] + ab[64 + c + 1];
    v.z = v.z * ab[c + 2] + ab[64 + c + 2];
    v.w = v.w * ab[c + 3] + ab[64 + c + 3];
    ((float4*)out)[i] = v;
}

// ---------------------------------------------------------------------------
extern "C" void kernel_launch(void* const* d_in, const int* in_sizes, int n_in,
                              void* d_out, int out_size)
{
    const float* x      = (const float*)d_in[0];
    const float* skip   = (const float*)d_in[1];
    const int*   nbr_t  = (const int*)d_in[2];
    const int*   nbr_up = (const int*)d_in[3];
    const int*   nbr1   = (const int*)d_in[4];
    const int*   nbr2   = (const int*)d_in[5];
    const int*   nbr3   = (const int*)d_in[6];
    const float* Wt     = (const float*)d_in[7];
    const float* Wu     = (const float*)d_in[8];
    const float* W1     = (const float*)d_in[9];
    const float* W2     = (const float*)d_in[10];
    const float* W3     = (const float*)d_in[11];
    const float* gt = (const float*)d_in[12]; const float* bt = (const float*)d_in[13];
    const float* g1 = (const float*)d_in[14]; const float* b1 = (const float*)d_in[15];
    const float* g2 = (const float*)d_in[16]; const float* b2 = (const float*)d_in[17];
    const float* g3 = (const float*)d_in[18]; const float* b3 = (const float*)d_in[19];

    const int N_in  = in_sizes[0] / 128;   // 80000
    const int N_out = in_sizes[1] / 64;    // 200000
    float* out = (float*)d_out;

    float *h_, *u_, *t1_, *t2_, *t3_, *part_, *ab_;
    uint32_t* bimg_;
    cudaGetSymbolAddress((void**)&h_,    g_h);
    cudaGetSymbolAddress((void**)&u_,    g_u);
    cudaGetSymbolAddress((void**)&t1_,   g_t1);
    cudaGetSymbolAddress((void**)&t2_,   g_t2);
    cudaGetSymbolAddress((void**)&t3_,   g_t3);
    cudaGetSymbolAddress((void**)&part_, g_part);
    cudaGetSymbolAddress((void**)&ab_,   g_ab);
    cudaGetSymbolAddress((void**)&bimg_, g_Bimg);

    cudaFuncSetAttribute(conv_mma<27, 128, false, 0>, cudaFuncAttributeMaxDynamicSharedMemorySize, SMEM_BYTES);
    cudaFuncSetAttribute(conv_mma<27,  64, true,  1>, cudaFuncAttributeMaxDynamicSharedMemorySize, SMEM_BYTES);
    cudaFuncSetAttribute(conv_mma< 9,  64, false, 0>, cudaFuncAttributeMaxDynamicSharedMemorySize, SMEM_BYTES);
    cudaFuncSetAttribute(conv_mma< 9,  64, true,  0>, cudaFuncAttributeMaxDynamicSharedMemorySize, SMEM_BYTES);
    cudaFuncSetAttribute(conv_mma<27,  64, true,  0>, cudaFuncAttributeMaxDynamicSharedMemorySize, SMEM_BYTES);

    const int gin  = (N_in  + 127) / 128;   // 625
    const int gout = (N_out + 127) / 128;   // 1563

    // 1. trans conv (Cin=128) + lrelu -> g_h ; BN stats -> ab[0]
    transpose_W<<<(27 * 4 * 1024 + 255) / 256, 256>>>(Wt, bimg_, 27 * 4 * 1024);
    conv_mma<27, 128, false, 0><<<gin, 256, SMEM_BYTES>>>(x, bimg_, nbr_t, nullptr, nullptr, h_, N_in, N_in);
    reduce_stats<<<RED_BLOCKS, 256>>>(h_, N_in, part_);
    finalize_stats<<<1, 64>>>(part_, RED_BLOCKS, 1.0f / N_in, gt, bt, ab_ + 0);

    // 2. inverse conv (gather of BN'd h) + skip -> g_u
    transpose_W<<<(27 * 2 * 1024 + 255) / 256, 256>>>(Wu, bimg_, 27 * 2 * 1024);
    conv_mma<27, 64, true, 1><<<gout, 256, SMEM_BYTES>>>(h_, bimg_, nbr_up, ab_ + 0, skip, u_, N_in, N_out);

    // 3. conv1 + lrelu -> t1 ; stats -> ab[1]
    transpose_W<<<(9 * 2 * 1024 + 255) / 256, 256>>>(W1, bimg_, 9 * 2 * 1024);
    conv_mma<9, 64, false, 0><<<gout, 256, SMEM_BYTES>>>(u_, bimg_, nbr1, nullptr, nullptr, t1_, N_out, N_out);
    reduce_stats<<<RED_BLOCKS, 256>>>(t1_, N_out, part_);
    finalize_stats<<<1, 64>>>(part_, RED_BLOCKS, 1.0f / N_out, g1, b1, ab_ + 128);

    // 4. conv2 (gather applies BN1) + lrelu -> t2 ; stats -> ab[2]
    transpose_W<<<(9 * 2 * 1024 + 255) / 256, 256>>>(W2, bimg_, 9 * 2 * 1024);
    conv_mma<9, 64, true, 0><<<gout, 256, SMEM_BYTES>>>(t1_, bimg_, nbr2, ab_ + 128, nullptr, t2_, N_out, N_out);
    reduce_stats<<<RED_BLOCKS, 256>>>(t2_, N_out, part_);
    finalize_stats<<<1, 64>>>(part_, RED_BLOCKS, 1.0f / N_out, g2, b2, ab_ + 256);

    // 5. conv3 (gather applies BN2) + lrelu -> t3 ; stats -> ab[3]
    transpose_W<<<(27 * 2 * 1024 + 255) / 256, 256>>>(W3, bimg_, 27 * 2 * 1024);
    conv_mma<27, 64, true, 0><<<gout, 256, SMEM_BYTES>>>(t2_, bimg_, nbr3, ab_ + 256, nullptr, t3_, N_out, N_out);
    reduce_stats<<<RED_BLOCKS, 256>>>(t3_, N_out, part_);
    finalize_stats<<<1, 64>>>(part_, RED_BLOCKS, 1.0f / N_out, g3, b3, ab_ + 384);

    // 6. final BN3 apply -> d_out
    const int total4 = N_out * 16;
    apply_affine<<<(total4 + 255) / 256, 256>>>(t3_, ab_ + 384, out, total4);
}

// round 7
// speedup vs baseline: 1.8042x; 1.6644x over previous
#include <cuda_runtime.h>
#include <cuda_bf16.h>
#include <cstdint>

#define SLOPE 0.01f
#define BN_EPS 1e-5f

#define MAX_NIN   80000
#define MAX_NOUT  200000
#define RED_BLOCKS 240

// Scratch (static device globals — no allocation allowed)
__device__ float    g_h [MAX_NIN  * 64];
__device__ float    g_u [MAX_NOUT * 64];
__device__ float    g_t1[MAX_NOUT * 64];
__device__ float    g_t2[MAX_NOUT * 64];
__device__ float    g_t3[MAX_NOUT * 64];
__device__ float    g_part[RED_BLOCKS * 128];
__device__ float    g_ab[4 * 128];              // per BN stage: a[64], b[64]
__device__ uint32_t g_Bimg[27 * 4 * 2048];      // split/packed/swizzled bf16 weights
__device__ uint32_t g_s0[MAX_NOUT * 64];        // split bf16 feature buffers (ping)
__device__ uint32_t g_s1[MAX_NOUT * 64];        // (pong)

// ---------------------------------------------------------------------------
// helpers
// ---------------------------------------------------------------------------
__device__ __forceinline__ uint32_t packbf(float a, float b) {
    __nv_bfloat162 t = __floats2bfloat162_rn(a, b);   // .x in low 16 bits
    return *reinterpret_cast<uint32_t*>(&t);
}
__device__ __forceinline__ uint32_t smem_u32(const void* p) {
    uint32_t a;
    asm("{ .reg .u64 t; cvta.to.shared.u64 t, %1; cvt.u32.u64 %0, t; }" : "=r"(a) : "l"(p));
    return a;
}

// m16n8k16 bf16 MMA (sm_80+ path; valid on compute_103)
__device__ __forceinline__ void mma_bf16(float* c, const uint32_t* a, const uint32_t* b) {
    asm volatile(
        "mma.sync.aligned.m16n8k16.row.col.f32.bf16.bf16.f32 "
        "{%0,%1,%2,%3}, {%4,%5,%6,%7}, {%8,%9}, {%0,%1,%2,%3};"
        : "+f"(c[0]), "+f"(c[1]), "+f"(c[2]), "+f"(c[3])
        : "r"(a[0]), "r"(a[1]), "r"(a[2]), "r"(a[3]), "r"(b[0]), "r"(b[1]));
}

#define LDSM4(R0, R1, R2, R3, addr) \
    asm volatile("ldmatrix.sync.aligned.m8n8.x4.shared.b16 {%0,%1,%2,%3}, [%4];" \
                 : "=r"(R0), "=r"(R1), "=r"(R2), "=r"(R3) : "r"(addr))

#define CP16(dst, src, sz) \
    asm volatile("cp.async.cg.shared.global [%0], [%1], 16, %2;" \
                 :: "r"(dst), "l"(src), "r"(sz) : "memory")
#define CP_COMMIT() asm volatile("cp.async.commit_group;" ::: "memory")

// Swizzled index into a [rows x 32] u32 tile (conflict-free for LDSM frags)
__device__ __forceinline__ int sidx(int row, int col) {
    return row * 32 + (col ^ ((row & 7) * 4));
}

// SMEM layout (u32 units): A 2x4096 (128x32), B 2x2048 (64x32)
#define F_A0 0
#define F_A1 4096
#define F_B0 8192
#define F_B1 10240
#define SMEM_BYTES (12288 * 4)

// ---------------------------------------------------------------------------
// Weight pre-transform: per chunk (one 32-wide Cin slice of one tap) build a
// 64x32 u32 tile: cols 0-15 = hi bf16x2 plane, 16-31 = lo plane, pre-swizzled.
// ---------------------------------------------------------------------------
__global__ void transpose_W(const float* __restrict__ W, uint32_t* __restrict__ Bimg,
                            int total)
{
    const int e = blockIdx.x * 256 + threadIdx.x;
    if (e >= total) return;
    const int chunk = e >> 10;
    const int kp    = (e >> 6) & 15;
    const int n     = e & 63;
    const int kbase = chunk * 32 + kp * 2;
    const float w0 = W[(size_t)kbase * 64 + n];
    const float w1 = W[(size_t)(kbase + 1) * 64 + n];
    const float h0 = __bfloat162float(__float2bfloat16_rn(w0));
    const float h1 = __bfloat162float(__float2bfloat16_rn(w1));
    uint32_t* dst = Bimg + (size_t)chunk * 2048;
    dst[sidx(n, kp)]      = packbf(w0, w1);
    dst[sidx(n, 16 + kp)] = packbf(w0 - h0, w1 - h1);
}

// ---------------------------------------------------------------------------
// Feature pre-split: fp32 [N, C] (+ optional BN affine) -> packed bf16 hi/lo.
// Point-major layout: u32[0..C/2) = hi pairs, u32[C/2..C) = lo pairs.
// ---------------------------------------------------------------------------
__global__ __launch_bounds__(256)
void split_feats(const float* __restrict__ in, const float* __restrict__ ab,
                 uint32_t* __restrict__ outp, int N, int C)
{
    const int i = blockIdx.x * 256 + threadIdx.x;
    if (i >= N * (C / 4)) return;
    const int p = i / (C / 4);
    const int q = i - p * (C / 4);
    float4 v = ((const float4*)in)[i];
    if (ab) {
        const int ch = q * 4;
        v.x = v.x * ab[ch + 0] + ab[64 + ch + 0];
        v.y = v.y * ab[ch + 1] + ab[64 + ch + 1];
        v.z = v.z * ab[ch + 2] + ab[64 + ch + 2];
        v.w = v.w * ab[ch + 3] + ab[64 + ch + 3];
    }
    const float hx = __bfloat162float(__float2bfloat16_rn(v.x));
    const float hy = __bfloat162float(__float2bfloat16_rn(v.y));
    const float hz = __bfloat162float(__float2bfloat16_rn(v.z));
    const float hw = __bfloat162float(__float2bfloat16_rn(v.w));
    uint32_t* base = outp + (size_t)p * C;
    *(uint2*)&base[q * 2]         = make_uint2(packbf(v.x, v.y), packbf(v.z, v.w));
    *(uint2*)&base[C / 2 + q * 2] = make_uint2(packbf(v.x - hx, v.y - hy),
                                               packbf(v.z - hz, v.w - hw));
}

// ---------------------------------------------------------------------------
// bf16 split-2 gather-GEMM conv (3 MMA terms: HH + H*Blo + Lo*Bh).
// Tile: 128 output points x 64 Cout; 8 warps (4x2), warp tile 32x32.
// K in 32-float chunks: cp.async gathers pre-split bf16 rows straight into
// swizzled SMEM (sentinel rows zero-filled via src-size=0), double-buffered;
// fragments loaded with ldmatrix.x4.
// MODE 0: out = lrelu(acc)    MODE 1: out = acc + skip
// ---------------------------------------------------------------------------
template<int KK, int CIN, int MODE>
__global__ __launch_bounds__(256)
void conv_mma(const uint32_t* __restrict__ feats,   // split bf16 features
              const uint32_t* __restrict__ Bimg,
              const int*   __restrict__ nbr,
              const float* __restrict__ skip,
              float*       __restrict__ out,
              int Nsrc, int Nout)
{
    constexpr int NSUB = CIN / 32;
    constexpr int NCH  = KK * NSUB;

    extern __shared__ uint32_t smu[];
    const uint32_t sb = smem_u32(smu);

    const int tid  = threadIdx.x;
    const int lane = tid & 31;
    const int wid  = tid >> 5;
    const int g    = lane >> 2, t4 = lane & 3;
    const int wm   = wid & 3,  wn  = wid >> 2;
    const int n0   = blockIdx.x * 128;
    const int row  = tid & 127, h = tid >> 7;

    float acc[2][4][4];
    #pragma unroll
    for (int mm = 0; mm < 2; ++mm)
        #pragma unroll
        for (int nn = 0; nn < 4; ++nn)
            #pragma unroll
            for (int q = 0; q < 4; ++q) acc[mm][nn][q] = 0.f;

    auto issue = [&](int c) {
        const int k = c / NSUB, s = c - k * NSUB;
        const uint32_t Ab = sb + ((c & 1) ? F_A1 : F_A0) * 4;
        const uint32_t Bb = sb + ((c & 1) ? F_B1 : F_B0) * 4;
        const int gr = n0 + row;
        int idx = Nsrc;
        if (gr < Nout) idx = nbr[(size_t)k * Nout + gr];
        const bool valid = (unsigned)idx < (unsigned)Nsrc;
        const int sz = valid ? 16 : 0;
        const uint32_t* srcp = feats + (size_t)(valid ? idx : 0) * CIN + s * 16 + h * 8;
        // A: hi plane (cols 0-15), lo plane (cols 16-31)
        CP16(Ab + sidx(row, h * 8 + 0) * 4,      srcp + 0,           sz);
        CP16(Ab + sidx(row, h * 8 + 4) * 4,      srcp + 4,           sz);
        CP16(Ab + sidx(row, 16 + h * 8 + 0) * 4, srcp + CIN / 2 + 0, sz);
        CP16(Ab + sidx(row, 16 + h * 8 + 4) * 4, srcp + CIN / 2 + 4, sz);
        // B: pre-swizzled image, pure linear copy (512 x 16B)
        const uint32_t* bs = Bimg + (size_t)c * 2048;
        CP16(Bb + tid * 16,         bs + tid * 4,         16);
        CP16(Bb + (tid + 256) * 16, bs + (tid + 256) * 4, 16);
        CP_COMMIT();
    };

    auto compute = [&](int buf) {
        const uint32_t Ab = sb + (buf ? F_A1 : F_A0) * 4;
        const uint32_t Bb = sb + (buf ? F_B1 : F_B0) * 4;
        #pragma unroll
        for (int ks = 0; ks < 2; ++ks) {
            uint32_t ah[2][4], al[2][4], bh[2][4], bl[2][4];
            #pragma unroll
            for (int mm = 0; mm < 2; ++mm) {
                const int arow = wm * 32 + mm * 16 + (lane & 15);
                const int acol = ks * 8 + (lane >> 4) * 4;
                LDSM4(ah[mm][0], ah[mm][1], ah[mm][2], ah[mm][3],
                      Ab + sidx(arow, acol) * 4);
                LDSM4(al[mm][0], al[mm][1], al[mm][2], al[mm][3],
                      Ab + sidx(arow, acol + 16) * 4);
            }
            #pragma unroll
            for (int p = 0; p < 2; ++p) {
                const int brow = wn * 32 + p * 16 + ((lane >> 4) & 1) * 8 + (lane & 7);
                const int bcol = ks * 8 + ((lane >> 3) & 1) * 4;
                LDSM4(bh[p][0], bh[p][1], bh[p][2], bh[p][3],
                      Bb + sidx(brow, bcol) * 4);
                LDSM4(bl[p][0], bl[p][1], bl[p][2], bl[p][3],
                      Bb + sidx(brow, bcol + 16) * 4);
            }
            #pragma unroll
            for (int mm = 0; mm < 2; ++mm)
                #pragma unroll
                for (int nn = 0; nn < 4; ++nn) {
                    const int p = nn >> 1, off = (nn & 1) * 2;
                    mma_bf16(acc[mm][nn], ah[mm], &bh[p][off]);
                    mma_bf16(acc[mm][nn], ah[mm], &bl[p][off]);
                    mma_bf16(acc[mm][nn], al[mm], &bh[p][off]);
                }
        }
    };

    issue(0);
    issue(1);
    #pragma unroll 1
    for (int c = 0; c < NCH; ++c) {
        if (c < NCH - 1) asm volatile("cp.async.wait_group 1;" ::: "memory");
        else             asm volatile("cp.async.wait_group 0;" ::: "memory");
        __syncthreads();                       // all warps' chunk-c data visible
        compute(c & 1);
        __syncthreads();                       // all warps done reading buf
        if (c + 2 < NCH) issue(c + 2);
    }

    // --- epilogue ---
    #pragma unroll
    for (int mm = 0; mm < 2; ++mm) {
        #pragma unroll
        for (int half = 0; half < 2; ++half) {
            const int r = n0 + wm * 32 + mm * 16 + g + half * 8;
            if (r < Nout) {
                #pragma unroll
                for (int nn = 0; nn < 4; ++nn) {
                    float v0 = acc[mm][nn][half * 2 + 0];
                    float v1 = acc[mm][nn][half * 2 + 1];
                    const int col = wn * 32 + nn * 8 + t4 * 2;
                    if (MODE == 1) {
                        const float2 s2 = *(const float2*)&skip[(size_t)r * 64 + col];
                        v0 += s2.x; v1 += s2.y;
                    } else {
                        v0 = v0 >= 0.f ? v0 : SLOPE * v0;
                        v1 = v1 >= 0.f ? v1 : SLOPE * v1;
                    }
                    *(float2*)&out[(size_t)r * 64 + col] = make_float2(v0, v1);
                }
            }
        }
    }
}

// ---------------------------------------------------------------------------
// BN stats (deterministic, two-stage)
// ---------------------------------------------------------------------------
__global__ __launch_bounds__(256)
void reduce_stats(const float* __restrict__ t, int N, float* __restrict__ partial)
{
    const int ch  = threadIdx.x & 63;
    const int sub = threadIdx.x >> 6;
    float s = 0.f, ss = 0.f;
    for (int row = blockIdx.x * 4 + sub; row < N; row += gridDim.x * 4) {
        const float v = t[(size_t)row * 64 + ch];
        s += v; ss += v * v;
    }
    __shared__ float sh[2][4][64];
    sh[0][sub][ch] = s;
    sh[1][sub][ch] = ss;
    __syncthreads();
    if (threadIdx.x < 64) {
        partial[blockIdx.x * 128 + ch]      = sh[0][0][ch] + sh[0][1][ch] + sh[0][2][ch] + sh[0][3][ch];
        partial[blockIdx.x * 128 + 64 + ch] = sh[1][0][ch] + sh[1][1][ch] + sh[1][2][ch] + sh[1][3][ch];
    }
}

// Parallel finalize: 256 threads (4 partial-sums per channel), fp64, fixed order.
__global__ __launch_bounds__(256)
void finalize_stats(const float* __restrict__ partial, int nblk, float invN,
                    const float* __restrict__ gamma, const float* __restrict__ beta,
                    float* __restrict__ ab)
{
    __shared__ double sh[4][128];
    const int ch = threadIdx.x & 63, part = threadIdx.x >> 6;
    double s = 0.0, ss = 0.0;
    for (int b = part; b < nblk; b += 4) {
        s  += (double)partial[b * 128 + ch];
        ss += (double)partial[b * 128 + 64 + ch];
    }
    sh[part][ch]      = s;
    sh[part][64 + ch] = ss;
    __syncthreads();
    if (threadIdx.x < 64) {
        const double S  = sh[0][ch] + sh[1][ch] + sh[2][ch] + sh[3][ch];
        const double SS = sh[0][64 + ch] + sh[1][64 + ch] + sh[2][64 + ch] + sh[3][64 + ch];
        const float m   = (float)(S * (double)invN);
        const float var = (float)(SS * (double)invN) - m * m;
        const float inv = rsqrtf(var + BN_EPS);
        const float a   = gamma[ch] * inv;
        ab[ch]      = a;
        ab[64 + ch] = beta[ch] - m * a;
    }
}

__global__ __launch_bounds__(256)
void apply_affine(const float* __restrict__ t, const float* __restrict__ ab,
                  float* __restrict__ out, int total4)
{
    const int i = blockIdx.x * blockDim.x + threadIdx.x;
    if (i >= total4) return;
    float4 v = ((const float4*)t)[i];
    const int c = (i & 15) * 4;
    v.x = v.x * ab[c + 0] + ab[64 + c + 0];
    v.y = v.y * ab[c + 1] + ab[64 + c + 1];
    v.z = v.z * ab[c + 2] + ab[64 + c + 2];
    v.w = v.w * ab[c + 3] + ab[64 + c + 3];
    ((float4*)out)[i] = v;
}

// ---------------------------------------------------------------------------
extern "C" void kernel_launch(void* const* d_in, const int* in_sizes, int n_in,
                              void* d_out, int out_size)
{
    const float* x      = (const float*)d_in[0];
    const float* skip   = (const float*)d_in[1];
    const int*   nbr_t  = (const int*)d_in[2];
    const int*   nbr_up = (const int*)d_in[3];
    const int*   nbr1   = (const int*)d_in[4];
    const int*   nbr2   = (const int*)d_in[5];
    const int*   nbr3   = (const int*)d_in[6];
    const float* Wt     = (const float*)d_in[7];
    const float* Wu     = (const float*)d_in[8];
    const float* W1     = (const float*)d_in[9];
    const float* W2     = (const float*)d_in[10];
    const float* W3     = (const float*)d_in[11];
    const float* gt = (const float*)d_in[12]; const float* bt = (const float*)d_in[13];
    const float* g1 = (const float*)d_in[14]; const float* b1 = (const float*)d_in[15];
    const float* g2 = (const float*)d_in[16]; const float* b2 = (const float*)d_in[17];
    const float* g3 = (const float*)d_in[18]; const float* b3 = (const float*)d_in[19];

    const int N_in  = in_sizes[0] / 128;   // 80000
    const int N_out = in_sizes[1] / 64;    // 200000
    float* out = (float*)d_out;

    float *h_, *u_, *t1_, *t2_, *t3_, *part_, *ab_;
    uint32_t *bimg_, *s0_, *s1_;
    cudaGetSymbolAddress((void**)&h_,    g_h);
    cudaGetSymbolAddress((void**)&u_,    g_u);
    cudaGetSymbolAddress((void**)&t1_,   g_t1);
    cudaGetSymbolAddress((void**)&t2_,   g_t2);
    cudaGetSymbolAddress((void**)&t3_,   g_t3);
    cudaGetSymbolAddress((void**)&part_, g_part);
    cudaGetSymbolAddress((void**)&ab_,   g_ab);
    cudaGetSymbolAddress((void**)&bimg_, g_Bimg);
    cudaGetSymbolAddress((void**)&s0_,   g_s0);
    cudaGetSymbolAddress((void**)&s1_,   g_s1);

    cudaFuncSetAttribute(conv_mma<27, 128, 0>, cudaFuncAttributeMaxDynamicSharedMemorySize, SMEM_BYTES);
    cudaFuncSetAttribute(conv_mma<27,  64, 1>, cudaFuncAttributeMaxDynamicSharedMemorySize, SMEM_BYTES);
    cudaFuncSetAttribute(conv_mma< 9,  64, 0>, cudaFuncAttributeMaxDynamicSharedMemorySize, SMEM_BYTES);
    cudaFuncSetAttribute(conv_mma<27,  64, 0>, cudaFuncAttributeMaxDynamicSharedMemorySize, SMEM_BYTES);

    const int gin  = (N_in  + 127) / 128;   // 625
    const int gout = (N_out + 127) / 128;   // 1563

    // 0. split x (Cin=128, no affine) -> s0
    split_feats<<<(N_in * 32 + 255) / 256, 256>>>(x, nullptr, s0_, N_in, 128);

    // 1. trans conv + lrelu -> g_h ; BN stats -> ab[0] ; split(h, ab0) -> s1
    transpose_W<<<(27 * 4 * 1024 + 255) / 256, 256>>>(Wt, bimg_, 27 * 4 * 1024);
    conv_mma<27, 128, 0><<<gin, 256, SMEM_BYTES>>>(s0_, bimg_, nbr_t, nullptr, h_, N_in, N_in);
    reduce_stats<<<RED_BLOCKS, 256>>>(h_, N_in, part_);
    finalize_stats<<<1, 256>>>(part_, RED_BLOCKS, 1.0f / N_in, gt, bt, ab_ + 0);
    split_feats<<<(N_in * 16 + 255) / 256, 256>>>(h_, ab_ + 0, s1_, N_in, 64);

    // 2. inverse conv + skip -> g_u ; split(u) -> s0
    transpose_W<<<(27 * 2 * 1024 + 255) / 256, 256>>>(Wu, bimg_, 27 * 2 * 1024);
    conv_mma<27, 64, 1><<<gout, 256, SMEM_BYTES>>>(s1_, bimg_, nbr_up, skip, u_, N_in, N_out);
    split_feats<<<(N_out * 16 + 255) / 256, 256>>>(u_, nullptr, s0_, N_out, 64);

    // 3. conv1 + lrelu -> t1 ; stats -> ab[1] ; split(t1, ab1) -> s1
    transpose_W<<<(9 * 2 * 1024 + 255) / 256, 256>>>(W1, bimg_, 9 * 2 * 1024);
    conv_mma<9, 64, 0><<<gout, 256, SMEM_BYTES>>>(s0_, bimg_, nbr1, nullptr, t1_, N_out, N_out);
    reduce_stats<<<RED_BLOCKS, 256>>>(t1_, N_out, part_);
    finalize_stats<<<1, 256>>>(part_, RED_BLOCKS, 1.0f / N_out, g1, b1, ab_ + 128);
    split_feats<<<(N_out * 16 + 255) / 256, 256>>>(t1_, ab_ + 128, s1_, N_out, 64);

    // 4. conv2 + lrelu -> t2 ; stats -> ab[2] ; split(t2, ab2) -> s0
    transpose_W<<<(9 * 2 * 1024 + 255) / 256, 256>>>(W2, bimg_, 9 * 2 * 1024);
    conv_mma<9, 64, 0><<<gout, 256, SMEM_BYTES>>>(s1_, bimg_, nbr2, nullptr, t2_, N_out, N_out);
    reduce_stats<<<RED_BLOCKS, 256>>>(t2_, N_out, part_);
    finalize_stats<<<1, 256>>>(part_, RED_BLOCKS, 1.0f / N_out, g2, b2, ab_ + 256);
    split_feats<<<(N_out * 16 + 255) / 256, 256>>>(t2_, ab_ + 256, s0_, N_out, 64);

    // 5. conv3 + lrelu -> t3 ; stats -> ab[3]
    transpose_W<<<(27 * 2 * 1024 + 255) / 256, 256>>>(W3, bimg_, 27 * 2 * 1024);
    conv_mma<27, 64, 0><<<gout, 256, SMEM_BYTES>>>(s0_, bimg_, nbr3, nullptr, t3_, N_out, N_out);
    reduce_stats<<<RED_BLOCKS, 256>>>(t3_, N_out, part_);
    finalize_stats<<<1, 256>>>(part_, RED_BLOCKS, 1.0f / N_out, g3, b3, ab_ + 384);

    // 6. final BN3 apply -> d_out
    const int total4 = N_out * 16;
    apply_affine<<<(total4 + 255) / 256, 256>>>(t3_, ab_ + 384, out, total4);
}

// round 8
// speedup vs baseline: 1.8091x; 1.0027x over previous
#include <cuda_runtime.h>
#include <cuda_bf16.h>
#include <cstdint>

#define SLOPE 0.01f
#define BN_EPS 1e-5f

#define MAX_NIN   80000
#define MAX_NOUT  200000
#define MAX_BLK   1600

// Scratch (static device globals — no allocation allowed)
__device__ float    g_h [MAX_NIN  * 64];
__device__ float    g_t1[MAX_NOUT * 64];
__device__ float    g_t2[MAX_NOUT * 64];
__device__ float    g_t3[MAX_NOUT * 64];
__device__ float    g_part[MAX_BLK * 128];
__device__ float    g_ab[4 * 128];              // per BN stage: a[64], b[64]
__device__ uint32_t g_Bimg[27 * 4 * 2048];      // split/packed/swizzled bf16 weights
__device__ uint32_t g_s0[MAX_NOUT * 64];        // split bf16 feature buffers (ping)
__device__ uint32_t g_s1[MAX_NOUT * 64];        // (pong)

// ---------------------------------------------------------------------------
// helpers
// ---------------------------------------------------------------------------
__device__ __forceinline__ uint32_t packbf(float a, float b) {
    __nv_bfloat162 t = __floats2bfloat162_rn(a, b);   // .x in low 16 bits
    return *reinterpret_cast<uint32_t*>(&t);
}
__device__ __forceinline__ uint32_t smem_u32(const void* p) {
    uint32_t a;
    asm("{ .reg .u64 t; cvta.to.shared.u64 t, %1; cvt.u32.u64 %0, t; }" : "=r"(a) : "l"(p));
    return a;
}

// m16n8k16 bf16 MMA
__device__ __forceinline__ void mma_bf16(float* c, const uint32_t* a, const uint32_t* b) {
    asm volatile(
        "mma.sync.aligned.m16n8k16.row.col.f32.bf16.bf16.f32 "
        "{%0,%1,%2,%3}, {%4,%5,%6,%7}, {%8,%9}, {%0,%1,%2,%3};"
        : "+f"(c[0]), "+f"(c[1]), "+f"(c[2]), "+f"(c[3])
        : "r"(a[0]), "r"(a[1]), "r"(a[2]), "r"(a[3]), "r"(b[0]), "r"(b[1]));
}

#define LDSM4(R0, R1, R2, R3, addr) \
    asm volatile("ldmatrix.sync.aligned.m8n8.x4.shared.b16 {%0,%1,%2,%3}, [%4];" \
                 : "=r"(R0), "=r"(R1), "=r"(R2), "=r"(R3) : "r"(addr))

#define CP16(dst, src, sz) \
    asm volatile("cp.async.cg.shared.global [%0], [%1], 16, %2;" \
                 :: "r"(dst), "l"(src), "r"(sz) : "memory")
#define CP_COMMIT() asm volatile("cp.async.commit_group;" ::: "memory")

// Swizzled index into a [rows x 32] u32 tile (conflict-free for LDSM frags)
__device__ __forceinline__ int sidx(int row, int col) {
    return row * 32 + (col ^ ((row & 7) * 4));
}

// SMEM (u32 units): A 4x4096 (128x32 each) at 0, B 4x2048 (64x32) at 16384
#define F_BBASE 16384
#define SMEM_BYTES (24576 * 4)

// ---------------------------------------------------------------------------
// Weight pre-transform: per chunk build a 64x32 u32 tile:
// cols 0-15 = hi bf16x2 plane, 16-31 = lo plane, pre-swizzled.
// ---------------------------------------------------------------------------
__global__ void transpose_W(const float* __restrict__ W, uint32_t* __restrict__ Bimg,
                            int total)
{
    const int e = blockIdx.x * 256 + threadIdx.x;
    if (e >= total) return;
    const int chunk = e >> 10;
    const int kp    = (e >> 6) & 15;
    const int n     = e & 63;
    const int kbase = chunk * 32 + kp * 2;
    const float w0 = W[(size_t)kbase * 64 + n];
    const float w1 = W[(size_t)(kbase + 1) * 64 + n];
    const float h0 = __bfloat162float(__float2bfloat16_rn(w0));
    const float h1 = __bfloat162float(__float2bfloat16_rn(w1));
    uint32_t* dst = Bimg + (size_t)chunk * 2048;
    dst[sidx(n, kp)]      = packbf(w0, w1);
    dst[sidx(n, 16 + kp)] = packbf(w0 - h0, w1 - h1);
}

// ---------------------------------------------------------------------------
// Feature pre-split: fp32 [N, C] (+ optional BN affine) -> packed bf16 hi/lo.
// Point-major: u32[0..C/2) = hi pairs, u32[C/2..C) = lo pairs.
// ---------------------------------------------------------------------------
__global__ __launch_bounds__(256)
void split_feats(const float* __restrict__ in, const float* __restrict__ ab,
                 uint32_t* __restrict__ outp, int N, int C)
{
    const int i = blockIdx.x * 256 + threadIdx.x;
    if (i >= N * (C / 4)) return;
    const int p = i / (C / 4);
    const int q = i - p * (C / 4);
    float4 v = ((const float4*)in)[i];
    if (ab) {
        const int ch = q * 4;
        v.x = v.x * ab[ch + 0] + ab[64 + ch + 0];
        v.y = v.y * ab[ch + 1] + ab[64 + ch + 1];
        v.z = v.z * ab[ch + 2] + ab[64 + ch + 2];
        v.w = v.w * ab[ch + 3] + ab[64 + ch + 3];
    }
    const float hx = __bfloat162float(__float2bfloat16_rn(v.x));
    const float hy = __bfloat162float(__float2bfloat16_rn(v.y));
    const float hz = __bfloat162float(__float2bfloat16_rn(v.z));
    const float hw = __bfloat162float(__float2bfloat16_rn(v.w));
    uint32_t* base = outp + (size_t)p * C;
    *(uint2*)&base[q * 2]         = make_uint2(packbf(v.x, v.y), packbf(v.z, v.w));
    *(uint2*)&base[C / 2 + q * 2] = make_uint2(packbf(v.x - hx, v.y - hy),
                                               packbf(v.z - hz, v.w - hw));
}

// ---------------------------------------------------------------------------
// bf16 split-2 gather-GEMM conv (3 MMA terms).
// Tile: 128 output points x 64 Cout; 8 warps (4x2), warp tile 32x32.
// 4-stage cp.async pipeline, ONE __syncthreads per 32-K chunk.
// MODE 0: out = lrelu(acc), fp32 store + per-block BN stats partials
// MODE 1: u = acc + skip, stored directly as split bf16 hi/lo (no fp32)
// ---------------------------------------------------------------------------
template<int KK, int CIN, int MODE>
__global__ __launch_bounds__(256)
void conv_mma(const uint32_t* __restrict__ feats,   // split bf16 features
              const uint32_t* __restrict__ Bimg,
              const int*   __restrict__ nbr,
              const float* __restrict__ skip,
              float*       __restrict__ out,
              uint32_t*    __restrict__ sout,
              float*       __restrict__ partials,
              int Nsrc, int Nout)
{
    constexpr int NSUB = CIN / 32;
    constexpr int NCH  = KK * NSUB;

    extern __shared__ uint32_t smu[];
    const uint32_t sb = smem_u32(smu);

    const int tid  = threadIdx.x;
    const int lane = tid & 31;
    const int wid  = tid >> 5;
    const int g    = lane >> 2, t4 = lane & 3;
    const int wm   = wid & 3,  wn  = wid >> 2;
    const int n0   = blockIdx.x * 128;
    const int row  = tid & 127, h = tid >> 7;

    float acc[2][4][4];
    #pragma unroll
    for (int mm = 0; mm < 2; ++mm)
        #pragma unroll
        for (int nn = 0; nn < 4; ++nn)
            #pragma unroll
            for (int q = 0; q < 4; ++q) acc[mm][nn][q] = 0.f;

    auto issue = [&](int c) {
        const int k = c / NSUB, s = c - k * NSUB;
        const int buf = c & 3;
        const uint32_t Ab = sb + (buf * 4096) * 4;
        const uint32_t Bb = sb + (F_BBASE + buf * 2048) * 4;
        const int gr = n0 + row;
        int idx = Nsrc;
        if (gr < Nout) idx = nbr[(size_t)k * Nout + gr];
        const bool valid = (unsigned)idx < (unsigned)Nsrc;
        const int sz = valid ? 16 : 0;
        const uint32_t* srcp = feats + (size_t)(valid ? idx : 0) * CIN + s * 16 + h * 8;
        CP16(Ab + sidx(row, h * 8 + 0) * 4,      srcp + 0,           sz);
        CP16(Ab + sidx(row, h * 8 + 4) * 4,      srcp + 4,           sz);
        CP16(Ab + sidx(row, 16 + h * 8 + 0) * 4, srcp + CIN / 2 + 0, sz);
        CP16(Ab + sidx(row, 16 + h * 8 + 4) * 4, srcp + CIN / 2 + 4, sz);
        const uint32_t* bs = Bimg + (size_t)c * 2048;
        CP16(Bb + tid * 16,         bs + tid * 4,         16);
        CP16(Bb + (tid + 256) * 16, bs + (tid + 256) * 4, 16);
        CP_COMMIT();
    };

    auto compute = [&](int buf) {
        const uint32_t Ab = sb + (buf * 4096) * 4;
        const uint32_t Bb = sb + (F_BBASE + buf * 2048) * 4;
        #pragma unroll
        for (int ks = 0; ks < 2; ++ks) {
            uint32_t ah[2][4], al[2][4], bh[2][4], bl[2][4];
            #pragma unroll
            for (int mm = 0; mm < 2; ++mm) {
                const int arow = wm * 32 + mm * 16 + (lane & 15);
                const int acol = ks * 8 + (lane >> 4) * 4;
                LDSM4(ah[mm][0], ah[mm][1], ah[mm][2], ah[mm][3],
                      Ab + sidx(arow, acol) * 4);
                LDSM4(al[mm][0], al[mm][1], al[mm][2], al[mm][3],
                      Ab + sidx(arow, acol + 16) * 4);
            }
            #pragma unroll
            for (int p = 0; p < 2; ++p) {
                const int brow = wn * 32 + p * 16 + ((lane >> 4) & 1) * 8 + (lane & 7);
                const int bcol = ks * 8 + ((lane >> 3) & 1) * 4;
                LDSM4(bh[p][0], bh[p][1], bh[p][2], bh[p][3],
                      Bb + sidx(brow, bcol) * 4);
                LDSM4(bl[p][0], bl[p][1], bl[p][2], bl[p][3],
                      Bb + sidx(brow, bcol + 16) * 4);
            }
            #pragma unroll
            for (int mm = 0; mm < 2; ++mm)
                #pragma unroll
                for (int nn = 0; nn < 4; ++nn) {
                    const int p = nn >> 1, off = (nn & 1) * 2;
                    mma_bf16(acc[mm][nn], ah[mm], &bh[p][off]);
                    mma_bf16(acc[mm][nn], ah[mm], &bl[p][off]);
                    mma_bf16(acc[mm][nn], al[mm], &bh[p][off]);
                }
        }
    };

    issue(0); issue(1); issue(2);
    #pragma unroll 1
    for (int c = 0; c < NCH; ++c) {
        if (c < NCH - 2)      asm volatile("cp.async.wait_group 2;" ::: "memory");
        else if (c == NCH - 2) asm volatile("cp.async.wait_group 1;" ::: "memory");
        else                   asm volatile("cp.async.wait_group 0;" ::: "memory");
        __syncthreads();
        compute(c & 3);
        if (c + 3 < NCH) issue(c + 3);
    }

    if (MODE == 1) {
        // --- epilogue: u = acc + skip, write split bf16 directly ---
        #pragma unroll
        for (int mm = 0; mm < 2; ++mm)
            #pragma unroll
            for (int half = 0; half < 2; ++half) {
                const int r = n0 + wm * 32 + mm * 16 + g + half * 8;
                if (r < Nout) {
                    uint32_t* base = sout + (size_t)r * 64;
                    #pragma unroll
                    for (int nn = 0; nn < 4; ++nn) {
                        const int col = wn * 32 + nn * 8 + t4 * 2;
                        const float2 s2 = *(const float2*)&skip[(size_t)r * 64 + col];
                        const float v0 = acc[mm][nn][half * 2 + 0] + s2.x;
                        const float v1 = acc[mm][nn][half * 2 + 1] + s2.y;
                        const float h0 = __bfloat162float(__float2bfloat16_rn(v0));
                        const float h1 = __bfloat162float(__float2bfloat16_rn(v1));
                        base[col / 2]      = packbf(v0, v1);
                        base[32 + col / 2] = packbf(v0 - h0, v1 - h1);
                    }
                }
            }
    } else {
        // --- epilogue: lrelu, fp32 store, per-block BN stats partials ---
        float sl[8], ql[8];
        #pragma unroll
        for (int j = 0; j < 8; ++j) { sl[j] = 0.f; ql[j] = 0.f; }
        #pragma unroll
        for (int mm = 0; mm < 2; ++mm)
            #pragma unroll
            for (int half = 0; half < 2; ++half) {
                const int r = n0 + wm * 32 + mm * 16 + g + half * 8;
                if (r < Nout) {
                    #pragma unroll
                    for (int nn = 0; nn < 4; ++nn) {
                        float v0 = acc[mm][nn][half * 2 + 0];
                        float v1 = acc[mm][nn][half * 2 + 1];
                        v0 = v0 >= 0.f ? v0 : SLOPE * v0;
                        v1 = v1 >= 0.f ? v1 : SLOPE * v1;
                        const int col = wn * 32 + nn * 8 + t4 * 2;
                        *(float2*)&out[(size_t)r * 64 + col] = make_float2(v0, v1);
                        sl[nn * 2 + 0] += v0; ql[nn * 2 + 0] += v0 * v0;
                        sl[nn * 2 + 1] += v1; ql[nn * 2 + 1] += v1 * v1;
                    }
                }
            }
        __syncthreads();                 // conv SMEM no longer needed; reuse
        float* red = (float*)smu;        // [2][64][32]
        const int ctr = wm * 8 + g;
        #pragma unroll
        for (int nn = 0; nn < 4; ++nn)
            #pragma unroll
            for (int b = 0; b < 2; ++b) {
                const int col = wn * 32 + nn * 8 + t4 * 2 + b;
                red[col * 32 + ctr]        = sl[nn * 2 + b];
                red[2048 + col * 32 + ctr] = ql[nn * 2 + b];
            }
        __syncthreads();
        if (tid < 128) {
            const int col = tid & 63, stat = tid >> 6;
            const float* src = red + stat * 2048 + col * 32;
            float s = 0.f;
            #pragma unroll
            for (int j = 0; j < 32; ++j) s += src[j];
            partials[blockIdx.x * 128 + stat * 64 + col] = s;
        }
    }
}

// ---------------------------------------------------------------------------
// Parallel finalize: 1024 threads (8 partial-slices per (ch,stat)), fp64,
// fixed order -> deterministic.
// ---------------------------------------------------------------------------
__global__ __launch_bounds__(1024)
void finalize_stats(const float* __restrict__ partial, int nblk, float invN,
                    const float* __restrict__ gamma, const float* __restrict__ beta,
                    float* __restrict__ ab)
{
    __shared__ double sh[8][128];
    const int owner = threadIdx.x & 127;          // ch + 64*stat
    const int part  = threadIdx.x >> 7;           // 0..7
    double s = 0.0;
    for (int b = part; b < nblk; b += 8)
        s += (double)partial[b * 128 + owner];
    sh[part][owner] = s;
    __syncthreads();
    if (threadIdx.x < 64) {
        const int ch = threadIdx.x;
        double S = 0.0, SS = 0.0;
        #pragma unroll
        for (int j = 0; j < 8; ++j) { S += sh[j][ch]; SS += sh[j][64 + ch]; }
        const float m   = (float)(S * (double)invN);
        const float var = (float)(SS * (double)invN) - m * m;
        const float inv = rsqrtf(var + BN_EPS);
        const float a   = gamma[ch] * inv;
        ab[ch]      = a;
        ab[64 + ch] = beta[ch] - m * a;
    }
}

__global__ __launch_bounds__(256)
void apply_affine(const float* __restrict__ t, const float* __restrict__ ab,
                  float* __restrict__ out, int total4)
{
    const int i = blockIdx.x * blockDim.x + threadIdx.x;
    if (i >= total4) return;
    float4 v = ((const float4*)t)[i];
    const int c = (i & 15) * 4;
    v.x = v.x * ab[c + 0] + ab[64 + c + 0];
    v.y = v.y * ab[c + 1] + ab[64 + c + 1];
    v.z = v.z * ab[c + 2] + ab[64 + c + 2];
    v.w = v.w * ab[c + 3] + ab[64 + c + 3];
    ((float4*)out)[i] = v;
}

// ---------------------------------------------------------------------------
extern "C" void kernel_launch(void* const* d_in, const int* in_sizes, int n_in,
                              void* d_out, int out_size)
{
    const float* x      = (const float*)d_in[0];
    const float* skip   = (const float*)d_in[1];
    const int*   nbr_t  = (const int*)d_in[2];
    const int*   nbr_up = (const int*)d_in[3];
    const int*   nbr1   = (const int*)d_in[4];
    const int*   nbr2   = (const int*)d_in[5];
    const int*   nbr3   = (const int*)d_in[6];
    const float* Wt     = (const float*)d_in[7];
    const float* Wu     = (const float*)d_in[8];
    const float* W1     = (const float*)d_in[9];
    const float* W2     = (const float*)d_in[10];
    const float* W3     = (const float*)d_in[11];
    const float* gt = (const float*)d_in[12]; const float* bt = (const float*)d_in[13];
    const float* g1 = (const float*)d_in[14]; const float* b1 = (const float*)d_in[15];
    const float* g2 = (const float*)d_in[16]; const float* b2 = (const float*)d_in[17];
    const float* g3 = (const float*)d_in[18]; const float* b3 = (const float*)d_in[19];

    const int N_in  = in_sizes[0] / 128;   // 80000
    const int N_out = in_sizes[1] / 64;    // 200000
    float* out = (float*)d_out;

    float *h_, *t1_, *t2_, *t3_, *part_, *ab_;
    uint32_t *bimg_, *s0_, *s1_;
    cudaGetSymbolAddress((void**)&h_,    g_h);
    cudaGetSymbolAddress((void**)&t1_,   g_t1);
    cudaGetSymbolAddress((void**)&t2_,   g_t2);
    cudaGetSymbolAddress((void**)&t3_,   g_t3);
    cudaGetSymbolAddress((void**)&part_, g_part);
    cudaGetSymbolAddress((void**)&ab_,   g_ab);
    cudaGetSymbolAddress((void**)&bimg_, g_Bimg);
    cudaGetSymbolAddress((void**)&s0_,   g_s0);
    cudaGetSymbolAddress((void**)&s1_,   g_s1);

    cudaFuncSetAttribute(conv_mma<27, 128, 0>, cudaFuncAttributeMaxDynamicSharedMemorySize, SMEM_BYTES);
    cudaFuncSetAttribute(conv_mma<27,  64, 1>, cudaFuncAttributeMaxDynamicSharedMemorySize, SMEM_BYTES);
    cudaFuncSetAttribute(conv_mma< 9,  64, 0>, cudaFuncAttributeMaxDynamicSharedMemorySize, SMEM_BYTES);
    cudaFuncSetAttribute(conv_mma<27,  64, 0>, cudaFuncAttributeMaxDynamicSharedMemorySize, SMEM_BYTES);

    const int gin  = (N_in  + 127) / 128;   // 625
    const int gout = (N_out + 127) / 128;   // 1563

    // 0. split x -> s0
    split_feats<<<(N_in * 32 + 255) / 256, 256>>>(x, nullptr, s0_, N_in, 128);

    // 1. trans conv + lrelu -> h (fp32) + stats partials ; finalize ab0 ; split
    transpose_W<<<(27 * 4 * 1024 + 255) / 256, 256>>>(Wt, bimg_, 27 * 4 * 1024);
    conv_mma<27, 128, 0><<<gin, 256, SMEM_BYTES>>>(s0_, bimg_, nbr_t, nullptr, h_, nullptr, part_, N_in, N_in);
    finalize_stats<<<1, 1024>>>(part_, gin, 1.0f / N_in, gt, bt, ab_ + 0);
    split_feats<<<(N_in * 16 + 255) / 256, 256>>>(h_, ab_ + 0, s1_, N_in, 64);

    // 2. inverse conv + skip -> split u directly into s0 (no fp32, no BN here)
    transpose_W<<<(27 * 2 * 1024 + 255) / 256, 256>>>(Wu, bimg_, 27 * 2 * 1024);
    conv_mma<27, 64, 1><<<gout, 256, SMEM_BYTES>>>(s1_, bimg_, nbr_up, skip, nullptr, s0_, nullptr, N_in, N_out);

    // 3. conv1 + lrelu -> t1 + stats ; finalize ab1 ; split
    transpose_W<<<(9 * 2 * 1024 + 255) / 256, 256>>>(W1, bimg_, 9 * 2 * 1024);
    conv_mma<9, 64, 0><<<gout, 256, SMEM_BYTES>>>(s0_, bimg_, nbr1, nullptr, t1_, nullptr, part_, N_out, N_out);
    finalize_stats<<<1, 1024>>>(part_, gout, 1.0f / N_out, g1, b1, ab_ + 128);
    split_feats<<<(N_out * 16 + 255) / 256, 256>>>(t1_, ab_ + 128, s1_, N_out, 64);

    // 4. conv2 + lrelu -> t2 + stats ; finalize ab2 ; split
    transpose_W<<<(9 * 2 * 1024 + 255) / 256, 256>>>(W2, bimg_, 9 * 2 * 1024);
    conv_mma<9, 64, 0><<<gout, 256, SMEM_BYTES>>>(s1_, bimg_, nbr2, nullptr, t2_, nullptr, part_, N_out, N_out);
    finalize_stats<<<1, 1024>>>(part_, gout, 1.0f / N_out, g2, b2, ab_ + 256);
    split_feats<<<(N_out * 16 + 255) / 256, 256>>>(t2_, ab_ + 256, s0_, N_out, 64);

    // 5. conv3 + lrelu -> t3 + stats ; finalize ab3
    transpose_W<<<(27 * 2 * 1024 + 255) / 256, 256>>>(W3, bimg_, 27 * 2 * 1024);
    conv_mma<27, 64, 0><<<gout, 256, SMEM_BYTES>>>(s0_, bimg_, nbr3, nullptr, t3_, nullptr, part_, N_out, N_out);
    finalize_stats<<<1, 1024>>>(part_, gout, 1.0f / N_out, g3, b3, ab_ + 384);

    // 6. final BN3 apply -> d_out
    const int total4 = N_out * 16;
    apply_affine<<<(total4 + 255) / 256, 256>>>(t3_, ab_ + 384, out, total4);
}

// round 9
// speedup vs baseline: 2.8344x; 1.5667x over previous
#include <cuda_runtime.h>
#include <cuda_bf16.h>
#include <cstdint>

#define SLOPE 0.01f
#define BN_EPS 1e-5f

#define MAX_NIN   80000
#define MAX_NOUT  200000
#define MAX_BLK   1600

// Scratch (static device globals — no allocation allowed)
__device__ float    g_h [MAX_NIN  * 64];
__device__ float    g_t1[MAX_NOUT * 64];
__device__ float    g_t2[MAX_NOUT * 64];
__device__ float    g_t3[MAX_NOUT * 64];
__device__ float    g_part[MAX_BLK * 128];
__device__ float    g_ab[4 * 128];              // per BN stage: a[64], b[64]
__device__ uint32_t g_Bimg[27 * 4 * 2048];      // split/packed/swizzled bf16 weights
__device__ uint32_t g_s0[MAX_NOUT * 64];        // split bf16 feature buffers (ping)
__device__ uint32_t g_s1[MAX_NOUT * 64];        // (pong)

// ---------------------------------------------------------------------------
// helpers
// ---------------------------------------------------------------------------
__device__ __forceinline__ uint32_t packbf(float a, float b) {
    __nv_bfloat162 t = __floats2bfloat162_rn(a, b);   // .x in low 16 bits
    return *reinterpret_cast<uint32_t*>(&t);
}
__device__ __forceinline__ uint32_t smem_u32(const void* p) {
    uint32_t a;
    asm("{ .reg .u64 t; cvta.to.shared.u64 t, %1; cvt.u32.u64 %0, t; }" : "=r"(a) : "l"(p));
    return a;
}

// m16n8k16 bf16 MMA
__device__ __forceinline__ void mma_bf16(float* c, const uint32_t* a, const uint32_t* b) {
    asm volatile(
        "mma.sync.aligned.m16n8k16.row.col.f32.bf16.bf16.f32 "
        "{%0,%1,%2,%3}, {%4,%5,%6,%7}, {%8,%9}, {%0,%1,%2,%3};"
        : "+f"(c[0]), "+f"(c[1]), "+f"(c[2]), "+f"(c[3])
        : "r"(a[0]), "r"(a[1]), "r"(a[2]), "r"(a[3]), "r"(b[0]), "r"(b[1]));
}

#define LDSM4(R0, R1, R2, R3, addr) \
    asm volatile("ldmatrix.sync.aligned.m8n8.x4.shared.b16 {%0,%1,%2,%3}, [%4];" \
                 : "=r"(R0), "=r"(R1), "=r"(R2), "=r"(R3) : "r"(addr))

#define CP16(dst, src, sz) \
    asm volatile("cp.async.cg.shared.global [%0], [%1], 16, %2;" \
                 :: "r"(dst), "l"(src), "r"(sz) : "memory")
#define CP_COMMIT() asm volatile("cp.async.commit_group;" ::: "memory")

// Swizzled index into a [rows x 32] u32 tile (conflict-free for LDSM frags)
__device__ __forceinline__ int sidx(int row, int col) {
    return row * 32 + (col ^ ((row & 7) * 4));
}

// SMEM (u32 units): A 4x4096 (128x32 each) at 0, B 4x2048 (64x32) at 16384
#define F_BBASE 16384
#define SMEM_BYTES (24576 * 4)

// ---------------------------------------------------------------------------
// Weight pre-transform: per chunk build a 64x32 u32 tile:
// cols 0-15 = hi bf16x2 plane, 16-31 = lo plane, pre-swizzled.
// ---------------------------------------------------------------------------
__global__ void transpose_W(const float* __restrict__ W, uint32_t* __restrict__ Bimg,
                            int total)
{
    const int e = blockIdx.x * 256 + threadIdx.x;
    if (e >= total) return;
    const int chunk = e >> 10;
    const int kp    = (e >> 6) & 15;
    const int n     = e & 63;
    const int kbase = chunk * 32 + kp * 2;
    const float w0 = W[(size_t)kbase * 64 + n];
    const float w1 = W[(size_t)(kbase + 1) * 64 + n];
    const float h0 = __bfloat162float(__float2bfloat16_rn(w0));
    const float h1 = __bfloat162float(__float2bfloat16_rn(w1));
    uint32_t* dst = Bimg + (size_t)chunk * 2048;
    dst[sidx(n, kp)]      = packbf(w0, w1);
    dst[sidx(n, 16 + kp)] = packbf(w0 - h0, w1 - h1);
}

// ---------------------------------------------------------------------------
// Feature pre-split: fp32 [N, C] (+ optional BN affine) -> packed bf16 hi/lo.
// Point-major: u32[0..C/2) = hi pairs, u32[C/2..C) = lo pairs.
// ---------------------------------------------------------------------------
__global__ __launch_bounds__(256)
void split_feats(const float* __restrict__ in, const float* __restrict__ ab,
                 uint32_t* __restrict__ outp, int N, int C)
{
    const int i = blockIdx.x * 256 + threadIdx.x;
    if (i >= N * (C / 4)) return;
    const int p = i / (C / 4);
    const int q = i - p * (C / 4);
    float4 v = ((const float4*)in)[i];
    if (ab) {
        const int ch = q * 4;
        v.x = v.x * ab[ch + 0] + ab[64 + ch + 0];
        v.y = v.y * ab[ch + 1] + ab[64 + ch + 1];
        v.z = v.z * ab[ch + 2] + ab[64 + ch + 2];
        v.w = v.w * ab[ch + 3] + ab[64 + ch + 3];
    }
    const float hx = __bfloat162float(__float2bfloat16_rn(v.x));
    const float hy = __bfloat162float(__float2bfloat16_rn(v.y));
    const float hz = __bfloat162float(__float2bfloat16_rn(v.z));
    const float hw = __bfloat162float(__float2bfloat16_rn(v.w));
    uint32_t* base = outp + (size_t)p * C;
    *(uint2*)&base[q * 2]         = make_uint2(packbf(v.x, v.y), packbf(v.z, v.w));
    *(uint2*)&base[C / 2 + q * 2] = make_uint2(packbf(v.x - hx, v.y - hy),
                                               packbf(v.z - hz, v.w - hw));
}

// ---------------------------------------------------------------------------
// bf16 split-2 gather-GEMM conv (3 MMA terms).
// Tile: 128 output points x 64 Cout; 8 warps (4x2), warp tile 32x32.
// 4-stage cp.async pipeline, one __syncthreads per 32-K chunk.
// Gather is wavefront-coalesced: 8 consecutive lanes of one cp.async
// instruction fetch the 8 16B pieces of ONE row (2 cache lines), instead of
// one-lane-per-row (8 lines per row).
// MODE 0: out = lrelu(acc), fp32 store + per-block BN stats partials
// MODE 1: u = acc + skip, stored directly as split bf16 hi/lo
// ---------------------------------------------------------------------------
template<int KK, int CIN, int MODE>
__global__ __launch_bounds__(256)
void conv_mma(const uint32_t* __restrict__ feats,   // split bf16 features
              const uint32_t* __restrict__ Bimg,
              const int*   __restrict__ nbr,
              const float* __restrict__ skip,
              float*       __restrict__ out,
              uint32_t*    __restrict__ sout,
              float*       __restrict__ partials,
              int Nsrc, int Nout)
{
    constexpr int NSUB = CIN / 32;
    constexpr int NCH  = KK * NSUB;

    extern __shared__ uint32_t smu[];
    const uint32_t sb = smem_u32(smu);

    const int tid  = threadIdx.x;
    const int lane = tid & 31;
    const int wid  = tid >> 5;
    const int g    = lane >> 2, t4 = lane & 3;
    const int wm   = wid & 3,  wn  = wid >> 2;
    const int n0   = blockIdx.x * 128;

    float acc[2][4][4];
    #pragma unroll
    for (int mm = 0; mm < 2; ++mm)
        #pragma unroll
        for (int nn = 0; nn < 4; ++nn)
            #pragma unroll
            for (int q = 0; q < 4; ++q) acc[mm][nn][q] = 0.f;

    auto issue = [&](int c) {
        const int k = c / NSUB, s = c - k * NSUB;
        const int buf = c & 3;
        const uint32_t Ab = sb + (buf * 4096) * 4;
        const uint32_t Bb = sb + (F_BBASE + buf * 2048) * 4;
        #pragma unroll
        for (int j = 0; j < 4; ++j) {
            const int piece = j * 256 + tid;        // 1024 pieces = 128 rows x 8
            const int prow  = piece >> 3;
            const int sub   = piece & 7;            // 0-3 hi 16B pieces, 4-7 lo
            const int gr = n0 + prow;
            int idx = Nsrc;
            if (gr < Nout) idx = nbr[(size_t)k * Nout + gr];   // 8 lanes share -> broadcast
            const bool valid = (unsigned)idx < (unsigned)Nsrc;
            const int sz = valid ? 16 : 0;
            const int soff = (sub < 4) ? (s * 16 + sub * 4)
                                       : (CIN / 2 + s * 16 + (sub - 4) * 4);
            const int col  = (sub < 4) ? (sub * 4) : (16 + (sub - 4) * 4);
            const uint32_t* srcp = feats + (size_t)(valid ? idx : 0) * CIN + soff;
            CP16(Ab + sidx(prow, col) * 4, srcp, sz);
        }
        const uint32_t* bs = Bimg + (size_t)c * 2048;
        CP16(Bb + tid * 16,         bs + tid * 4,         16);
        CP16(Bb + (tid + 256) * 16, bs + (tid + 256) * 4, 16);
        CP_COMMIT();
    };

    auto compute = [&](int buf) {
        const uint32_t Ab = sb + (buf * 4096) * 4;
        const uint32_t Bb = sb + (F_BBASE + buf * 2048) * 4;
        #pragma unroll
        for (int ks = 0; ks < 2; ++ks) {
            uint32_t ah[2][4], al[2][4], bh[2][4], bl[2][4];
            #pragma unroll
            for (int mm = 0; mm < 2; ++mm) {
                const int arow = wm * 32 + mm * 16 + (lane & 15);
                const int acol = ks * 8 + (lane >> 4) * 4;
                LDSM4(ah[mm][0], ah[mm][1], ah[mm][2], ah[mm][3],
                      Ab + sidx(arow, acol) * 4);
                LDSM4(al[mm][0], al[mm][1], al[mm][2], al[mm][3],
                      Ab + sidx(arow, acol + 16) * 4);
            }
            #pragma unroll
            for (int p = 0; p < 2; ++p) {
                const int brow = wn * 32 + p * 16 + ((lane >> 4) & 1) * 8 + (lane & 7);
                const int bcol = ks * 8 + ((lane >> 3) & 1) * 4;
                LDSM4(bh[p][0], bh[p][1], bh[p][2], bh[p][3],
                      Bb + sidx(brow, bcol) * 4);
                LDSM4(bl[p][0], bl[p][1], bl[p][2], bl[p][3],
                      Bb + sidx(brow, bcol + 16) * 4);
            }
            #pragma unroll
            for (int mm = 0; mm < 2; ++mm)
                #pragma unroll
                for (int nn = 0; nn < 4; ++nn) {
                    const int p = nn >> 1, off = (nn & 1) * 2;
                    mma_bf16(acc[mm][nn], ah[mm], &bh[p][off]);
                    mma_bf16(acc[mm][nn], ah[mm], &bl[p][off]);
                    mma_bf16(acc[mm][nn], al[mm], &bh[p][off]);
                }
        }
    };

    issue(0); issue(1); issue(2);
    #pragma unroll 1
    for (int c = 0; c < NCH; ++c) {
        if (c < NCH - 2)       asm volatile("cp.async.wait_group 2;" ::: "memory");
        else if (c == NCH - 2) asm volatile("cp.async.wait_group 1;" ::: "memory");
        else                   asm volatile("cp.async.wait_group 0;" ::: "memory");
        __syncthreads();
        compute(c & 3);
        if (c + 3 < NCH) issue(c + 3);
    }

    if (MODE == 1) {
        // --- epilogue: u = acc + skip, write split bf16 directly ---
        #pragma unroll
        for (int mm = 0; mm < 2; ++mm)
            #pragma unroll
            for (int half = 0; half < 2; ++half) {
                const int r = n0 + wm * 32 + mm * 16 + g + half * 8;
                if (r < Nout) {
                    uint32_t* base = sout + (size_t)r * 64;
                    #pragma unroll
                    for (int nn = 0; nn < 4; ++nn) {
                        const int col = wn * 32 + nn * 8 + t4 * 2;
                        const float2 s2 = *(const float2*)&skip[(size_t)r * 64 + col];
                        const float v0 = acc[mm][nn][half * 2 + 0] + s2.x;
                        const float v1 = acc[mm][nn][half * 2 + 1] + s2.y;
                        const float h0 = __bfloat162float(__float2bfloat16_rn(v0));
                        const float h1 = __bfloat162float(__float2bfloat16_rn(v1));
                        base[col / 2]      = packbf(v0, v1);
                        base[32 + col / 2] = packbf(v0 - h0, v1 - h1);
                    }
                }
            }
    } else {
        // --- epilogue: lrelu, fp32 store, per-block BN stats partials ---
        float sl[8], ql[8];
        #pragma unroll
        for (int j = 0; j < 8; ++j) { sl[j] = 0.f; ql[j] = 0.f; }
        #pragma unroll
        for (int mm = 0; mm < 2; ++mm)
            #pragma unroll
            for (int half = 0; half < 2; ++half) {
                const int r = n0 + wm * 32 + mm * 16 + g + half * 8;
                if (r < Nout) {
                    #pragma unroll
                    for (int nn = 0; nn < 4; ++nn) {
                        float v0 = acc[mm][nn][half * 2 + 0];
                        float v1 = acc[mm][nn][half * 2 + 1];
                        v0 = v0 >= 0.f ? v0 : SLOPE * v0;
                        v1 = v1 >= 0.f ? v1 : SLOPE * v1;
                        const int col = wn * 32 + nn * 8 + t4 * 2;
                        *(float2*)&out[(size_t)r * 64 + col] = make_float2(v0, v1);
                        sl[nn * 2 + 0] += v0; ql[nn * 2 + 0] += v0 * v0;
                        sl[nn * 2 + 1] += v1; ql[nn * 2 + 1] += v1 * v1;
                    }
                }
            }
        __syncthreads();                 // conv SMEM no longer needed; reuse
        float* red = (float*)smu;        // [2][64][32]
        const int ctr = wm * 8 + g;
        #pragma unroll
        for (int nn = 0; nn < 4; ++nn)
            #pragma unroll
            for (int b = 0; b < 2; ++b) {
                const int col = wn * 32 + nn * 8 + t4 * 2 + b;
                red[col * 32 + ctr]        = sl[nn * 2 + b];
                red[2048 + col * 32 + ctr] = ql[nn * 2 + b];
            }
        __syncthreads();
        if (tid < 128) {
            const int col = tid & 63, stat = tid >> 6;
            const float* src = red + stat * 2048 + col * 32;
            float s = 0.f;
            #pragma unroll
            for (int j = 0; j < 32; ++j) s += src[j];
            partials[blockIdx.x * 128 + stat * 64 + col] = s;
        }
    }
}

// ---------------------------------------------------------------------------
// Parallel finalize: grid = 64 blocks (one per channel), 256 threads.
// Threads 0-127 sum the S partials, 128-255 the SS partials; fixed-order
// tree reduction -> deterministic. Thread 0 writes a,b.
// ---------------------------------------------------------------------------
__global__ __launch_bounds__(256)
void finalize_stats(const float* __restrict__ partial, int nblk, float invN,
                    const float* __restrict__ gamma, const float* __restrict__ beta,
                    float* __restrict__ ab)
{
    __shared__ double sh[256];
    const int ch   = blockIdx.x;
    const int t    = threadIdx.x;
    const int half = t >> 7;           // 0: S, 1: SS
    const int tt   = t & 127;
    double s = 0.0;
    for (int b = tt; b < nblk; b += 128)
        s += (double)partial[b * 128 + half * 64 + ch];
    sh[t] = s;
    __syncthreads();
    #pragma unroll
    for (int off = 64; off >= 1; off >>= 1) {
        if (tt < off) sh[t] += sh[t + off];
        __syncthreads();
    }
    if (t == 0) {
        const double S  = sh[0];
        const double SS = sh[128];
        const float m   = (float)(S * (double)invN);
        const float var = (float)(SS * (double)invN) - m * m;
        const float inv = rsqrtf(var + BN_EPS);
        const float a   = gamma[ch] * inv;
        ab[ch]      = a;
        ab[64 + ch] = beta[ch] - m * a;
    }
}

__global__ __launch_bounds__(256)
void apply_affine(const float* __restrict__ t, const float* __restrict__ ab,
                  float* __restrict__ out, int total4)
{
    const int i = blockIdx.x * blockDim.x + threadIdx.x;
    if (i >= total4) return;
    float4 v = ((const float4*)t)[i];
    const int c = (i & 15) * 4;
    v.x = v.x * ab[c + 0] + ab[64 + c + 0];
    v.y = v.y * ab[c + 1] + ab[64 + c + 1];
    v.z = v.z * ab[c + 2] + ab[64 + c + 2];
    v.w = v.w * ab[c + 3] + ab[64 + c + 3];
    ((float4*)out)[i] = v;
}

// ---------------------------------------------------------------------------
extern "C" void kernel_launch(void* const* d_in, const int* in_sizes, int n_in,
                              void* d_out, int out_size)
{
    const float* x      = (const float*)d_in[0];
    const float* skip   = (const float*)d_in[1];
    const int*   nbr_t  = (const int*)d_in[2];
    const int*   nbr_up = (const int*)d_in[3];
    const int*   nbr1   = (const int*)d_in[4];
    const int*   nbr2   = (const int*)d_in[5];
    const int*   nbr3   = (const int*)d_in[6];
    const float* Wt     = (const float*)d_in[7];
    const float* Wu     = (const float*)d_in[8];
    const float* W1     = (const float*)d_in[9];
    const float* W2     = (const float*)d_in[10];
    const float* W3     = (const float*)d_in[11];
    const float* gt = (const float*)d_in[12]; const float* bt = (const float*)d_in[13];
    const float* g1 = (const float*)d_in[14]; const float* b1 = (const float*)d_in[15];
    const float* g2 = (const float*)d_in[16]; const float* b2 = (const float*)d_in[17];
    const float* g3 = (const float*)d_in[18]; const float* b3 = (const float*)d_in[19];

    const int N_in  = in_sizes[0] / 128;   // 80000
    const int N_out = in_sizes[1] / 64;    // 200000
    float* out = (float*)d_out;

    float *h_, *t1_, *t2_, *t3_, *part_, *ab_;
    uint32_t *bimg_, *s0_, *s1_;
    cudaGetSymbolAddress((void**)&h_,    g_h);
    cudaGetSymbolAddress((void**)&t1_,   g_t1);
    cudaGetSymbolAddress((void**)&t2_,   g_t2);
    cudaGetSymbolAddress((void**)&t3_,   g_t3);
    cudaGetSymbolAddress((void**)&part_, g_part);
    cudaGetSymbolAddress((void**)&ab_,   g_ab);
    cudaGetSymbolAddress((void**)&bimg_, g_Bimg);
    cudaGetSymbolAddress((void**)&s0_,   g_s0);
    cudaGetSymbolAddress((void**)&s1_,   g_s1);

    cudaFuncSetAttribute(conv_mma<27, 128, 0>, cudaFuncAttributeMaxDynamicSharedMemorySize, SMEM_BYTES);
    cudaFuncSetAttribute(conv_mma<27,  64, 1>, cudaFuncAttributeMaxDynamicSharedMemorySize, SMEM_BYTES);
    cudaFuncSetAttribute(conv_mma< 9,  64, 0>, cudaFuncAttributeMaxDynamicSharedMemorySize, SMEM_BYTES);
    cudaFuncSetAttribute(conv_mma<27,  64, 0>, cudaFuncAttributeMaxDynamicSharedMemorySize, SMEM_BYTES);

    const int gin  = (N_in  + 127) / 128;   // 625
    const int gout = (N_out + 127) / 128;   // 1563

    // 0. split x -> s0
    split_feats<<<(N_in * 32 + 255) / 256, 256>>>(x, nullptr, s0_, N_in, 128);

    // 1. trans conv + lrelu -> h (fp32) + stats partials ; finalize ab0 ; split
    transpose_W<<<(27 * 4 * 1024 + 255) / 256, 256>>>(Wt, bimg_, 27 * 4 * 1024);
    conv_mma<27, 128, 0><<<gin, 256, SMEM_BYTES>>>(s0_, bimg_, nbr_t, nullptr, h_, nullptr, part_, N_in, N_in);
    finalize_stats<<<64, 256>>>(part_, gin, 1.0f / N_in, gt, bt, ab_ + 0);
    split_feats<<<(N_in * 16 + 255) / 256, 256>>>(h_, ab_ + 0, s1_, N_in, 64);

    // 2. inverse conv + skip -> split u directly into s0
    transpose_W<<<(27 * 2 * 1024 + 255) / 256, 256>>>(Wu, bimg_, 27 * 2 * 1024);
    conv_mma<27, 64, 1><<<gout, 256, SMEM_BYTES>>>(s1_, bimg_, nbr_up, skip, nullptr, s0_, nullptr, N_in, N_out);

    // 3. conv1 + lrelu -> t1 + stats ; finalize ab1 ; split
    transpose_W<<<(9 * 2 * 1024 + 255) / 256, 256>>>(W1, bimg_, 9 * 2 * 1024);
    conv_mma<9, 64, 0><<<gout, 256, SMEM_BYTES>>>(s0_, bimg_, nbr1, nullptr, t1_, nullptr, part_, N_out, N_out);
    finalize_stats<<<64, 256>>>(part_, gout, 1.0f / N_out, g1, b1, ab_ + 128);
    split_feats<<<(N_out * 16 + 255) / 256, 256>>>(t1_, ab_ + 128, s1_, N_out, 64);

    // 4. conv2 + lrelu -> t2 + stats ; finalize ab2 ; split
    transpose_W<<<(9 * 2 * 1024 + 255) / 256, 256>>>(W2, bimg_, 9 * 2 * 1024);
    conv_mma<9, 64, 0><<<gout, 256, SMEM_BYTES>>>(s1_, bimg_, nbr2, nullptr, t2_, nullptr, part_, N_out, N_out);
    finalize_stats<<<64, 256>>>(part_, gout, 1.0f / N_out, g2, b2, ab_ + 256);
    split_feats<<<(N_out * 16 + 255) / 256, 256>>>(t2_, ab_ + 256, s0_, N_out, 64);

    // 5. conv3 + lrelu -> t3 + stats ; finalize ab3
    transpose_W<<<(27 * 2 * 1024 + 255) / 256, 256>>>(W3, bimg_, 27 * 2 * 1024);
    conv_mma<27, 64, 0><<<gout, 256, SMEM_BYTES>>>(s0_, bimg_, nbr3, nullptr, t3_, nullptr, part_, N_out, N_out);
    finalize_stats<<<64, 256>>>(part_, gout, 1.0f / N_out, g3, b3, ab_ + 384);

    // 6. final BN3 apply -> d_out
    const int total4 = N_out * 16;
    apply_affine<<<(total4 + 255) / 256, 256>>>(t3_, ab_ + 384, out, total4);
}